// round 7
// baseline (speedup 1.0000x reference)
#include <cuda_runtime.h>
#include <cuda_bf16.h>
#include <cstdint>

#define N_NODES 50000
#define N_EDGES 800000
#define D_IN    16
#define HID     128
#define D_OUT   4
#define N_LAYERS 3
#define LN_EPS  1e-5f

#define SCAN_BLOCKS 196   // ceil(50000/256)
#define CSR_BLOCKS  592   // must be fully co-resident (<=1184 on 148 SMs @256thr)

// Scratch (device globals: allocation-free, graph-capturable)
__device__ float g_h   [N_NODES * HID];
__device__ float g_hn  [N_NODES * HID];
__device__ float g_agg [N_NODES * HID];
__device__ __nv_bfloat16 g_Bhi[N_LAYERS * HID * 2 * HID];  // [l][n=128][k=256]
__device__ __nv_bfloat16 g_Blo[N_LAYERS * HID * 2 * HID];
__device__ float g_inv [N_NODES];
__device__ int   g_cnt [N_NODES];
__device__ int   g_off [N_NODES + 1];
__device__ int   g_cur [N_NODES];
__device__ int   g_bsum[SCAN_BLOCKS];
__device__ int   g_bpre[SCAN_BLOCKS];
__device__ int   g_esrc[N_EDGES];
__device__ int   g_bar_count;
__device__ int   g_bar_gen;

// ---------------------------------------------------------------------------
// bf16 mma.sync (base PTX, works on compute_103): D += A(16x16) * B(16x8)
// ---------------------------------------------------------------------------
__device__ __forceinline__ void mma_bf16(float* c, const uint32_t* a, const uint32_t* b) {
    asm volatile(
        "mma.sync.aligned.m16n8k16.row.col.f32.bf16.bf16.f32 "
        "{%0,%1,%2,%3}, {%4,%5,%6,%7}, {%8,%9}, {%0,%1,%2,%3};"
        : "+f"(c[0]), "+f"(c[1]), "+f"(c[2]), "+f"(c[3])
        : "r"(a[0]), "r"(a[1]), "r"(a[2]), "r"(a[3]), "r"(b[0]), "r"(b[1]));
}

// ---------------------------------------------------------------------------
// Manual grid barrier: all CSR_BLOCKS blocks are co-resident (checked sizing),
// so spin-wait is deadlock-free. Generation counter survives across calls.
// ---------------------------------------------------------------------------
__device__ __forceinline__ void gsync() {
    __syncthreads();
    __threadfence();
    if (threadIdx.x == 0) {
        int gen = atomicAdd(&g_bar_gen, 0);
        if (atomicAdd(&g_bar_count, 1) == CSR_BLOCKS - 1) {
            g_bar_count = 0;
            __threadfence();
            atomicAdd(&g_bar_gen, 1);
        } else {
            while (atomicAdd(&g_bar_gen, 0) == gen) {}
        }
    }
    __syncthreads();
}

// ---------------------------------------------------------------------------
// Whole CSR build in ONE kernel: zero -> count -> scan(3 phases) -> inv -> fill
// ---------------------------------------------------------------------------
__global__ void __launch_bounds__(256) k_csr(const int* __restrict__ src,
                                             const int* __restrict__ dst) {
    __shared__ int s[2][256];
    int b = blockIdx.x, t = threadIdx.x;
    int tid = b * 256 + t;
    int nt = CSR_BLOCKS * 256;

    // Phase 0: zero counts
    for (int i = tid; i < N_NODES; i += nt) g_cnt[i] = 0;
    gsync();

    // Phase 1: degree histogram
    for (int e = tid; e < N_EDGES; e += nt) atomicAdd(&g_cnt[dst[e]], 1);
    gsync();

    // Phase 2: per-256-chunk local exclusive scan (blocks 0..SCAN_BLOCKS-1)
    if (b < SCAN_BLOCKS) {
        int i = b * 256 + t;
        int v = (i < N_NODES) ? g_cnt[i] : 0;
        s[0][t] = v;
        __syncthreads();
        int p = 0;
#pragma unroll
        for (int off = 1; off < 256; off <<= 1) {
            int nv = s[p][t] + ((t >= off) ? s[p][t - off] : 0);
            s[p ^ 1][t] = nv;
            __syncthreads();
            p ^= 1;
        }
        if (i < N_NODES) g_off[i] = s[p][t] - v;
        if (t == 255) g_bsum[b] = s[p][255];
    }
    gsync();

    // Phase 3: scan of block sums (block 0)
    if (b == 0) {
        int v = (t < SCAN_BLOCKS) ? g_bsum[t] : 0;
        s[0][t] = v;
        __syncthreads();
        int p = 0;
#pragma unroll
        for (int off = 1; off < 256; off <<= 1) {
            int nv = s[p][t] + ((t >= off) ? s[p][t - off] : 0);
            s[p ^ 1][t] = nv;
            __syncthreads();
            p ^= 1;
        }
        if (t < SCAN_BLOCKS) g_bpre[t] = s[p][t] - v;
    }
    gsync();

    // Phase 4: finalize offsets, cursors, inv-degree
    for (int i = tid; i < N_NODES; i += nt) {
        int o = g_off[i] + g_bpre[i >> 8];
        g_off[i] = o;
        g_cur[i] = o;
        g_inv[i] = 1.0f / fmaxf((float)g_cnt[i], 1.0f);
    }
    if (tid == 0) g_off[N_NODES] = N_EDGES;
    gsync();

    // Phase 5: fill edge lists
    for (int e = tid; e < N_EDGES; e += nt) {
        int pos = atomicAdd(&g_cur[dst[e]], 1);
        g_esrc[pos] = src[e];
    }
}

// ---------------------------------------------------------------------------
// Weight transpose + bf16 hi/lo split:
// g_Bhi/lo[l][n][k] from Wcat[k][n] = (k<128 ? Wl[l][k][n] : Wr[l][k-128][n])
// ---------------------------------------------------------------------------
__global__ void k_wsplit(const float* __restrict__ Wl, const float* __restrict__ Wr) {
    __shared__ float s[32][33];
    int K0 = blockIdx.x * 32;
    int N0 = blockIdx.y * 32;
    int l = blockIdx.z;
    int tx = threadIdx.x, ty = threadIdx.y;
    const float* WlL = Wl + l * HID * HID;
    const float* WrL = Wr + l * HID * HID;
#pragma unroll
    for (int i = 0; i < 4; i++) {
        int k = K0 + ty + i * 8;
        int n = N0 + tx;
        s[ty + i * 8][tx] = (k < HID) ? WlL[k * HID + n] : WrL[(k - HID) * HID + n];
    }
    __syncthreads();
    __nv_bfloat16* Oh = g_Bhi + (size_t)l * HID * 2 * HID;
    __nv_bfloat16* Ol = g_Blo + (size_t)l * HID * 2 * HID;
#pragma unroll
    for (int i = 0; i < 4; i++) {
        int n = N0 + ty + i * 8;
        int k = K0 + tx;
        float v = s[tx][ty + i * 8];
        __nv_bfloat16 hi = __float2bfloat16_rn(v);
        Oh[(size_t)n * 256 + k] = hi;
        Ol[(size_t)n * 256 + k] = __float2bfloat16_rn(v - __bfloat162float(hi));
    }
}

// ---------------------------------------------------------------------------
// Warp-level LN of a 128-float row held as float4 per lane
// ---------------------------------------------------------------------------
__device__ __forceinline__ float4 warp_ln(float4 v, float4 gg, float4 bb) {
    float s = v.x + v.y + v.z + v.w;
#pragma unroll
    for (int o = 16; o; o >>= 1) s += __shfl_xor_sync(0xFFFFFFFFu, s, o);
    float mu = s * (1.0f / HID);
    float dx = v.x - mu, dy = v.y - mu, dz = v.z - mu, dw = v.w - mu;
    float q = dx * dx + dy * dy + dz * dz + dw * dw;
#pragma unroll
    for (int o = 16; o; o >>= 1) q += __shfl_xor_sync(0xFFFFFFFFu, q, o);
    float rs = rsqrtf(q * (1.0f / HID) + LN_EPS);
    float4 r;
    r.x = dx * rs * gg.x + bb.x;
    r.y = dy * rs * gg.y + bb.y;
    r.z = dz * rs * gg.z + bb.z;
    r.w = dw * rs * gg.w + bb.w;
    return r;
}

// ---------------------------------------------------------------------------
// h = x @ W_in + b_in  (50000 x 16 @ 16 x 128) with fused LN(layer 0) -> g_hn
// ---------------------------------------------------------------------------
__global__ void k_in_gemm(const float* __restrict__ x,
                          const float* __restrict__ W,
                          const float* __restrict__ b,
                          const float* __restrict__ lng,
                          const float* __restrict__ lnb) {
    __shared__ float xs[16][D_IN];
    __shared__ float Ws[D_IN][HID];
    __shared__ float hs[16][HID];
    int tid = threadIdx.x;
    int m0 = blockIdx.x * 16;

#pragma unroll
    for (int i = 0; i < 2; i++) {
        int idx = tid + i * 256;
        ((float4*)&Ws[0][0])[idx] = ((const float4*)W)[idx];
    }
    {
        int r = tid >> 4, k = tid & 15;
        xs[r][k] = x[(size_t)(m0 + r) * D_IN + k];
    }
    __syncthreads();

    int col = tid & 127;
    int rh  = tid >> 7;
    float wc[D_IN];
#pragma unroll
    for (int k = 0; k < D_IN; k++) wc[k] = Ws[k][col];
    float bb = b[col];

#pragma unroll
    for (int r = 0; r < 8; r++) {
        int row = rh * 8 + r;
        float acc = bb;
#pragma unroll
        for (int k = 0; k < D_IN; k++) acc += xs[row][k] * wc[k];
        g_h[(size_t)(m0 + row) * HID + col] = acc;
        hs[row][col] = acc;
    }
    __syncthreads();

    int wid = tid >> 5, lane = tid & 31;
    float4 gg = *(const float4*)(lng + lane * 4);
    float4 lb = *(const float4*)(lnb + lane * 4);
#pragma unroll
    for (int i = 0; i < 2; i++) {
        int row = wid * 2 + i;
        float4 v = ((const float4*)hs[row])[lane];
        float4 o = warp_ln(v, gg, lb);
        ((float4*)(g_hn + (size_t)(m0 + row) * HID))[lane] = o;
    }
}

// ---------------------------------------------------------------------------
// Standalone LayerNorm: hn = LN(h) * g + b.  One warp per row.
// ---------------------------------------------------------------------------
__global__ void k_ln(const float* __restrict__ g, const float* __restrict__ b) {
    int warp = (blockIdx.x * blockDim.x + threadIdx.x) >> 5;
    int lane = threadIdx.x & 31;
    if (warp >= N_NODES) return;
    float4 v = ((const float4*)(g_h + (size_t)warp * HID))[lane];
    float4 gg = *(const float4*)(g + lane * 4);
    float4 bb = *(const float4*)(b + lane * 4);
    float4 o = warp_ln(v, gg, bb);
    ((float4*)(g_hn + (size_t)warp * HID))[lane] = o;
}

// ---------------------------------------------------------------------------
// Aggregate (CSR): agg[n] = (sum over incoming edges of hn[src]) * inv_deg[n]
// One warp per node; explicit 8-wide unroll for MLP, dual accumulator chains.
// ---------------------------------------------------------------------------
__global__ void k_agg() {
    int node = (blockIdx.x * blockDim.x + threadIdx.x) >> 5;
    int lane = threadIdx.x & 31;
    if (node >= N_NODES) return;

    int beg = g_off[node];
    int end = g_off[node + 1];
    float4 acc0 = make_float4(0.f, 0.f, 0.f, 0.f);
    float4 acc1 = make_float4(0.f, 0.f, 0.f, 0.f);

    for (int e = beg; e < end; e += 32) {
        int rem = end - e;
        if (rem > 32) rem = 32;
        int sidx = (lane < rem) ? g_esrc[e + lane] : 0;
        int j = 0;
        for (; j + 8 <= rem; j += 8) {
            int s0 = __shfl_sync(0xFFFFFFFFu, sidx, j + 0);
            int s1 = __shfl_sync(0xFFFFFFFFu, sidx, j + 1);
            int s2 = __shfl_sync(0xFFFFFFFFu, sidx, j + 2);
            int s3 = __shfl_sync(0xFFFFFFFFu, sidx, j + 3);
            int s4 = __shfl_sync(0xFFFFFFFFu, sidx, j + 4);
            int s5 = __shfl_sync(0xFFFFFFFFu, sidx, j + 5);
            int s6 = __shfl_sync(0xFFFFFFFFu, sidx, j + 6);
            int s7 = __shfl_sync(0xFFFFFFFFu, sidx, j + 7);
            float4 v0 = ((const float4*)(g_hn + (size_t)s0 * HID))[lane];
            float4 v1 = ((const float4*)(g_hn + (size_t)s1 * HID))[lane];
            float4 v2 = ((const float4*)(g_hn + (size_t)s2 * HID))[lane];
            float4 v3 = ((const float4*)(g_hn + (size_t)s3 * HID))[lane];
            float4 v4 = ((const float4*)(g_hn + (size_t)s4 * HID))[lane];
            float4 v5 = ((const float4*)(g_hn + (size_t)s5 * HID))[lane];
            float4 v6 = ((const float4*)(g_hn + (size_t)s6 * HID))[lane];
            float4 v7 = ((const float4*)(g_hn + (size_t)s7 * HID))[lane];
            acc0.x += v0.x; acc0.y += v0.y; acc0.z += v0.z; acc0.w += v0.w;
            acc1.x += v1.x; acc1.y += v1.y; acc1.z += v1.z; acc1.w += v1.w;
            acc0.x += v2.x; acc0.y += v2.y; acc0.z += v2.z; acc0.w += v2.w;
            acc1.x += v3.x; acc1.y += v3.y; acc1.z += v3.z; acc1.w += v3.w;
            acc0.x += v4.x; acc0.y += v4.y; acc0.z += v4.z; acc0.w += v4.w;
            acc1.x += v5.x; acc1.y += v5.y; acc1.z += v5.z; acc1.w += v5.w;
            acc0.x += v6.x; acc0.y += v6.y; acc0.z += v6.z; acc0.w += v6.w;
            acc1.x += v7.x; acc1.y += v7.y; acc1.z += v7.z; acc1.w += v7.w;
        }
        for (; j < rem; j++) {
            int s = __shfl_sync(0xFFFFFFFFu, sidx, j);
            float4 v = ((const float4*)(g_hn + (size_t)s * HID))[lane];
            acc0.x += v.x; acc0.y += v.y; acc0.z += v.z; acc0.w += v.w;
        }
    }

    float inv = g_inv[node];
    float4 acc;
    acc.x = (acc0.x + acc1.x) * inv;
    acc.y = (acc0.y + acc1.y) * inv;
    acc.z = (acc0.z + acc1.z) * inv;
    acc.w = (acc0.w + acc1.w) * inv;
    ((float4*)(g_agg + (size_t)node * HID))[lane] = acc;
}

// ---------------------------------------------------------------------------
// Layer GEMM via mma.sync bf16x3:  h = relu(h + [agg | hn] @ Wcat + bl)
// CTA tile 128x128, K=256 in 16 chunks of 16. 512 threads = 16 warps (4x4),
// warp tile 32x32. 2-stage smem double buffer, 48B pitch.
// ---------------------------------------------------------------------------
#define LPITCH 48
#define STG    6144          // 128 rows * 48B, one stage of one array
#define SM_A_HI 0
#define SM_A_LO 12288
#define SM_B_HI 24576
#define SM_B_LO 36864
#define LAYER_SMEM 49152

__global__ void __launch_bounds__(512) k_layer(int l, const float* __restrict__ bl) {
    extern __shared__ char sm[];
    int tid = threadIdx.x;
    int lane = tid & 31, wid = tid >> 5;
    int wm = wid & 3, wn = wid >> 2;
    int m0 = blockIdx.x * 128;

    const __nv_bfloat16* Bh_ = g_Bhi + (size_t)l * HID * 2 * HID;
    const __nv_bfloat16* Bl_ = g_Blo + (size_t)l * HID * 2 * HID;

    float C[2][4][4];
#pragma unroll
    for (int mt = 0; mt < 2; mt++)
#pragma unroll
        for (int nt = 0; nt < 4; nt++)
#pragma unroll
            for (int j = 0; j < 4; j++) C[mt][nt][j] = 0.0f;

    int s_r = tid >> 2, s_q = tid & 3;
    int arow = m0 + s_r;
    if (arow >= N_NODES) arow = N_NODES - 1;

    float4 av;
    uint2 bhv, blv;
    av  = *(const float4*)(g_agg + (size_t)arow * HID + s_q * 4);
    bhv = *(const uint2*)(Bh_ + (size_t)s_r * 256 + s_q * 4);
    blv = *(const uint2*)(Bl_ + (size_t)s_r * 256 + s_q * 4);

    for (int c = 0; c < 16; c++) {
        int st = c & 1;
        char* Ah = sm + SM_A_HI + st * STG;
        char* Al = sm + SM_A_LO + st * STG;
        char* Bh = sm + SM_B_HI + st * STG;
        char* Bl = sm + SM_B_LO + st * STG;

        {
            __nv_bfloat162 h0 = __floats2bfloat162_rn(av.x, av.y);
            __nv_bfloat162 h1 = __floats2bfloat162_rn(av.z, av.w);
            float lx = av.x - __bfloat162float(h0.x);
            float ly = av.y - __bfloat162float(h0.y);
            float lz = av.z - __bfloat162float(h1.x);
            float lw = av.w - __bfloat162float(h1.y);
            __nv_bfloat162 l0 = __floats2bfloat162_rn(lx, ly);
            __nv_bfloat162 l1 = __floats2bfloat162_rn(lz, lw);
            uint2 ph, pl;
            ph.x = *(uint32_t*)&h0; ph.y = *(uint32_t*)&h1;
            pl.x = *(uint32_t*)&l0; pl.y = *(uint32_t*)&l1;
            *(uint2*)(Ah + s_r * LPITCH + s_q * 8) = ph;
            *(uint2*)(Al + s_r * LPITCH + s_q * 8) = pl;
            *(uint2*)(Bh + s_r * LPITCH + s_q * 8) = bhv;
            *(uint2*)(Bl + s_r * LPITCH + s_q * 8) = blv;
        }
        __syncthreads();

        if (c < 15) {
            int cn = c + 1;
            const float* Asrc = (cn < 8) ? (g_agg + cn * 16) : (g_hn + (cn - 8) * 16);
            av  = *(const float4*)(Asrc + (size_t)arow * HID + s_q * 4);
            bhv = *(const uint2*)(Bh_ + (size_t)s_r * 256 + cn * 16 + s_q * 4);
            blv = *(const uint2*)(Bl_ + (size_t)s_r * 256 + cn * 16 + s_q * 4);
        }

        uint32_t a_hi[2][4], a_lo[2][4], b_hi[4][2], b_lo[4][2];
#pragma unroll
        for (int mt = 0; mt < 2; mt++) {
            int off = (wm * 32 + mt * 16 + (lane >> 2)) * LPITCH + (lane & 3) * 4;
            a_hi[mt][0] = *(uint32_t*)(Ah + off);
            a_hi[mt][1] = *(uint32_t*)(Ah + off + 8 * LPITCH);
            a_hi[mt][2] = *(uint32_t*)(Ah + off + 16);
            a_hi[mt][3] = *(uint32_t*)(Ah + off + 8 * LPITCH + 16);
            a_lo[mt][0] = *(uint32_t*)(Al + off);
            a_lo[mt][1] = *(uint32_t*)(Al + off + 8 * LPITCH);
            a_lo[mt][2] = *(uint32_t*)(Al + off + 16);
            a_lo[mt][3] = *(uint32_t*)(Al + off + 8 * LPITCH + 16);
        }
#pragma unroll
        for (int nt = 0; nt < 4; nt++) {
            int off = (wn * 32 + nt * 8 + (lane >> 2)) * LPITCH + (lane & 3) * 4;
            b_hi[nt][0] = *(uint32_t*)(Bh + off);
            b_hi[nt][1] = *(uint32_t*)(Bh + off + 16);
            b_lo[nt][0] = *(uint32_t*)(Bl + off);
            b_lo[nt][1] = *(uint32_t*)(Bl + off + 16);
        }

#pragma unroll
        for (int mt = 0; mt < 2; mt++)
#pragma unroll
            for (int nt = 0; nt < 4; nt++) {
                mma_bf16(C[mt][nt], a_hi[mt], b_hi[nt]);
                mma_bf16(C[mt][nt], a_hi[mt], b_lo[nt]);
                mma_bf16(C[mt][nt], a_lo[mt], b_hi[nt]);
            }
        __syncthreads();
    }

    // Epilogue: residual + bias + relu into g_h
#pragma unroll
    for (int mt = 0; mt < 2; mt++) {
        int r0 = m0 + wm * 32 + mt * 16 + (lane >> 2);
#pragma unroll
        for (int half = 0; half < 2; half++) {
            int r = r0 + half * 8;
            if (r < N_NODES) {
#pragma unroll
                for (int nt = 0; nt < 4; nt++) {
                    int cb = wn * 32 + nt * 8 + (lane & 3) * 2;
                    float* hp = g_h + (size_t)r * HID + cb;
                    float2 h2 = *(float2*)hp;
                    float2 bb = *(const float2*)(bl + cb);
                    float2 o;
                    o.x = fmaxf(h2.x + C[mt][nt][half * 2 + 0] + bb.x, 0.0f);
                    o.y = fmaxf(h2.y + C[mt][nt][half * 2 + 1] + bb.y, 0.0f);
                    *(float2*)hp = o;
                }
            }
        }
    }
}

// ---------------------------------------------------------------------------
// out = h @ W_out + b_out   (50000 x 128 @ 128 x 4), one warp per node
// ---------------------------------------------------------------------------
__global__ void k_out(const float* __restrict__ Wo,
                      const float* __restrict__ bo,
                      float* __restrict__ out) {
    __shared__ float Ws[HID * D_OUT];
    int tid = threadIdx.x;
    for (int i = tid; i < HID * D_OUT; i += blockDim.x) Ws[i] = Wo[i];
    __syncthreads();

    int warp = (blockIdx.x * blockDim.x + tid) >> 5;
    int lane = tid & 31;
    if (warp >= N_NODES) return;

    const float* hr = g_h + (size_t)warp * HID;
    float a0 = 0.f, a1 = 0.f, a2 = 0.f, a3 = 0.f;
#pragma unroll
    for (int t = 0; t < 4; t++) {
        int k = lane + t * 32;
        float hv = hr[k];
        a0 += hv * Ws[k * D_OUT + 0];
        a1 += hv * Ws[k * D_OUT + 1];
        a2 += hv * Ws[k * D_OUT + 2];
        a3 += hv * Ws[k * D_OUT + 3];
    }
#pragma unroll
    for (int o = 16; o; o >>= 1) {
        a0 += __shfl_xor_sync(0xFFFFFFFFu, a0, o);
        a1 += __shfl_xor_sync(0xFFFFFFFFu, a1, o);
        a2 += __shfl_xor_sync(0xFFFFFFFFu, a2, o);
        a3 += __shfl_xor_sync(0xFFFFFFFFu, a3, o);
    }
    if (lane == 0) {
        float4 r;
        r.x = a0 + bo[0];
        r.y = a1 + bo[1];
        r.z = a2 + bo[2];
        r.w = a3 + bo[3];
        *(float4*)(out + (size_t)warp * D_OUT) = r;
    }
}

// ---------------------------------------------------------------------------
extern "C" void kernel_launch(void* const* d_in, const int* in_sizes, int n_in,
                              void* d_out, int out_size) {
    const float* x     = (const float*)d_in[0];
    const int*   ei    = (const int*)  d_in[1];
    const float* W_in  = (const float*)d_in[2];
    const float* b_in  = (const float*)d_in[3];
    const float* Wl    = (const float*)d_in[4];
    const float* bl    = (const float*)d_in[5];
    const float* Wr    = (const float*)d_in[6];
    const float* ln_g  = (const float*)d_in[7];
    const float* ln_b  = (const float*)d_in[8];
    const float* W_out = (const float*)d_in[9];
    const float* b_out = (const float*)d_in[10];
    float* out = (float*)d_out;

    const int* src = ei;             // edge_index[0]
    const int* dst = ei + N_EDGES;   // edge_index[1]

    cudaFuncSetAttribute(k_layer, cudaFuncAttributeMaxDynamicSharedMemorySize, LAYER_SMEM);

    // Whole CSR build in one kernel (manual grid barrier; all blocks resident)
    k_csr<<<CSR_BLOCKS, 256>>>(src, dst);

    // Weight transpose + bf16 hi/lo split (once per call)
    {
        dim3 g(256 / 32, 128 / 32, N_LAYERS);
        dim3 b(32, 8);
        k_wsplit<<<g, b>>>(Wl, Wr);
    }

    // in_gemm with fused LN(layer 0)
    k_in_gemm<<<N_NODES / 16, 256>>>(x, W_in, b_in, ln_g, ln_b);

    for (int l = 0; l < N_LAYERS; l++) {
        k_agg<<<(N_NODES * 32 + 255) / 256, 256>>>();
        k_layer<<<(N_NODES + 127) / 128, 512, LAYER_SMEM>>>(l, bl + l * HID);
        if (l + 1 < N_LAYERS)
            k_ln<<<(N_NODES * 32 + 255) / 256, 256>>>(ln_g + (l + 1) * HID,
                                                      ln_b + (l + 1) * HID);
    }

    k_out<<<(N_NODES * 32 + 255) / 256, 256>>>(W_out, b_out, out);
}

// round 8
// speedup vs baseline: 1.0300x; 1.0300x over previous
#include <cuda_runtime.h>
#include <cuda_bf16.h>
#include <cuda_fp16.h>
#include <cstdint>

#define N_NODES 50000
#define N_EDGES 800000
#define D_IN    16
#define HID     128
#define D_OUT   4
#define N_LAYERS 3
#define LN_EPS  1e-5f

#define SCAN_BLOCKS 196   // ceil(50000/256)

// Scratch (device globals: allocation-free, graph-capturable)
__device__ float  g_h   [N_NODES * HID];
__device__ float  g_hn  [N_NODES * HID];
__device__ __half g_hnh [N_NODES * HID];   // fp16 mirror of hn for the gather
__device__ float  g_agg [N_NODES * HID];
__device__ __nv_bfloat16 g_Bhi[N_LAYERS * HID * 2 * HID];  // [l][n=128][k=256]
__device__ __nv_bfloat16 g_Blo[N_LAYERS * HID * 2 * HID];
__device__ float g_inv [N_NODES];
__device__ int   g_cnt [N_NODES];
__device__ int   g_off [N_NODES + 1];
__device__ int   g_cur [N_NODES];
__device__ int   g_bsum[SCAN_BLOCKS];
__device__ int   g_bpre[SCAN_BLOCKS];
__device__ int   g_esrc[N_EDGES];

// ---------------------------------------------------------------------------
// bf16 mma.sync (base PTX, works on compute_103): D += A(16x16) * B(16x8)
// ---------------------------------------------------------------------------
__device__ __forceinline__ void mma_bf16(float* c, const uint32_t* a, const uint32_t* b) {
    asm volatile(
        "mma.sync.aligned.m16n8k16.row.col.f32.bf16.bf16.f32 "
        "{%0,%1,%2,%3}, {%4,%5,%6,%7}, {%8,%9}, {%0,%1,%2,%3};"
        : "+f"(c[0]), "+f"(c[1]), "+f"(c[2]), "+f"(c[3])
        : "r"(a[0]), "r"(a[1]), "r"(a[2]), "r"(a[3]), "r"(b[0]), "r"(b[1]));
}

// ---------------------------------------------------------------------------
// CSR build: histogram -> scan -> fill
// ---------------------------------------------------------------------------
__global__ void k_zero_cnt() {
    int i = blockIdx.x * blockDim.x + threadIdx.x;
    if (i < N_NODES) g_cnt[i] = 0;
}

__global__ void k_count(const int* __restrict__ dst) {
    int e = blockIdx.x * blockDim.x + threadIdx.x;
    if (e < N_EDGES) atomicAdd(&g_cnt[dst[e]], 1);
}

__global__ void k_scan1() {
    __shared__ int s[2][256];
    int b = blockIdx.x, t = threadIdx.x;
    int i = b * 256 + t;
    int v = (i < N_NODES) ? g_cnt[i] : 0;
    s[0][t] = v;
    __syncthreads();
    int p = 0;
#pragma unroll
    for (int off = 1; off < 256; off <<= 1) {
        int nv = s[p][t] + ((t >= off) ? s[p][t - off] : 0);
        s[p ^ 1][t] = nv;
        __syncthreads();
        p ^= 1;
    }
    if (i < N_NODES) g_off[i] = s[p][t] - v;
    if (t == 255) g_bsum[b] = s[p][255];
}

__global__ void k_scan2() {
    __shared__ int s[2][256];
    int t = threadIdx.x;
    int v = (t < SCAN_BLOCKS) ? g_bsum[t] : 0;
    s[0][t] = v;
    __syncthreads();
    int p = 0;
#pragma unroll
    for (int off = 1; off < 256; off <<= 1) {
        int nv = s[p][t] + ((t >= off) ? s[p][t - off] : 0);
        s[p ^ 1][t] = nv;
        __syncthreads();
        p ^= 1;
    }
    if (t < SCAN_BLOCKS) g_bpre[t] = s[p][t] - v;
}

__global__ void k_scan3() {
    int i = blockIdx.x * blockDim.x + threadIdx.x;
    if (i < N_NODES) {
        int o = g_off[i] + g_bpre[i >> 8];
        g_off[i] = o;
        g_cur[i] = o;
        g_inv[i] = 1.0f / fmaxf((float)g_cnt[i], 1.0f);
    }
    if (i == 0) g_off[N_NODES] = N_EDGES;
}

__global__ void k_fill(const int* __restrict__ src, const int* __restrict__ dst) {
    int e = blockIdx.x * blockDim.x + threadIdx.x;
    if (e < N_EDGES) {
        int pos = atomicAdd(&g_cur[dst[e]], 1);
        g_esrc[pos] = src[e];
    }
}

// ---------------------------------------------------------------------------
// Weight transpose + bf16 hi/lo split:
// g_Bhi/lo[l][n][k] from Wcat[k][n] = (k<128 ? Wl[l][k][n] : Wr[l][k-128][n])
// ---------------------------------------------------------------------------
__global__ void k_wsplit(const float* __restrict__ Wl, const float* __restrict__ Wr) {
    __shared__ float s[32][33];
    int K0 = blockIdx.x * 32;
    int N0 = blockIdx.y * 32;
    int l = blockIdx.z;
    int tx = threadIdx.x, ty = threadIdx.y;
    const float* WlL = Wl + l * HID * HID;
    const float* WrL = Wr + l * HID * HID;
#pragma unroll
    for (int i = 0; i < 4; i++) {
        int k = K0 + ty + i * 8;
        int n = N0 + tx;
        s[ty + i * 8][tx] = (k < HID) ? WlL[k * HID + n] : WrL[(k - HID) * HID + n];
    }
    __syncthreads();
    __nv_bfloat16* Oh = g_Bhi + (size_t)l * HID * 2 * HID;
    __nv_bfloat16* Ol = g_Blo + (size_t)l * HID * 2 * HID;
#pragma unroll
    for (int i = 0; i < 4; i++) {
        int n = N0 + ty + i * 8;
        int k = K0 + tx;
        float v = s[tx][ty + i * 8];
        __nv_bfloat16 hi = __float2bfloat16_rn(v);
        Oh[(size_t)n * 256 + k] = hi;
        Ol[(size_t)n * 256 + k] = __float2bfloat16_rn(v - __bfloat162float(hi));
    }
}

// ---------------------------------------------------------------------------
// h = x @ W_in + b_in    (50000 x 16 @ 16 x 128)
// ---------------------------------------------------------------------------
__global__ void k_in_gemm(const float* __restrict__ x,
                          const float* __restrict__ W,
                          const float* __restrict__ b) {
    __shared__ float xs[16][D_IN];
    __shared__ float Ws[D_IN][HID];
    int tid = threadIdx.x;
    int m0 = blockIdx.x * 16;

#pragma unroll
    for (int i = 0; i < 2; i++) {
        int idx = tid + i * 256;
        ((float4*)&Ws[0][0])[idx] = ((const float4*)W)[idx];
    }
    {
        int r = tid >> 4, k = tid & 15;
        xs[r][k] = x[(size_t)(m0 + r) * D_IN + k];
    }
    __syncthreads();

    int col = tid & 127;
    int rh  = tid >> 7;
    float wc[D_IN];
#pragma unroll
    for (int k = 0; k < D_IN; k++) wc[k] = Ws[k][col];
    float bb = b[col];

#pragma unroll
    for (int r = 0; r < 8; r++) {
        int row = rh * 8 + r;
        float acc = bb;
#pragma unroll
        for (int k = 0; k < D_IN; k++) acc += xs[row][k] * wc[k];
        g_h[(size_t)(m0 + row) * HID + col] = acc;
    }
}

// ---------------------------------------------------------------------------
// LayerNorm: hn = LN(h) * g + b, written BOTH fp32 (GEMM operand) and fp16
// (gather operand). One warp per row; lane handles a float4.
// ---------------------------------------------------------------------------
__global__ void k_ln(const float* __restrict__ g, const float* __restrict__ b) {
    int warp = (blockIdx.x * blockDim.x + threadIdx.x) >> 5;
    int lane = threadIdx.x & 31;
    if (warp >= N_NODES) return;

    float4 v = ((const float4*)(g_h + (size_t)warp * HID))[lane];
    float s = v.x + v.y + v.z + v.w;
#pragma unroll
    for (int o = 16; o; o >>= 1) s += __shfl_xor_sync(0xFFFFFFFFu, s, o);
    float mu = s * (1.0f / HID);

    float dx = v.x - mu, dy = v.y - mu, dz = v.z - mu, dw = v.w - mu;
    float q = dx * dx + dy * dy + dz * dz + dw * dw;
#pragma unroll
    for (int o = 16; o; o >>= 1) q += __shfl_xor_sync(0xFFFFFFFFu, q, o);
    float rs = rsqrtf(q * (1.0f / HID) + LN_EPS);

    int c = lane * 4;
    float4 gg = *(const float4*)(g + c);
    float4 bb = *(const float4*)(b + c);
    float4 o4;
    o4.x = dx * rs * gg.x + bb.x;
    o4.y = dy * rs * gg.y + bb.y;
    o4.z = dz * rs * gg.z + bb.z;
    o4.w = dw * rs * gg.w + bb.w;
    ((float4*)(g_hn + (size_t)warp * HID))[lane] = o4;

    __half2 hh0 = __floats2half2_rn(o4.x, o4.y);
    __half2 hh1 = __floats2half2_rn(o4.z, o4.w);
    uint2 hp;
    hp.x = *(uint32_t*)&hh0;
    hp.y = *(uint32_t*)&hh1;
    ((uint2*)(g_hnh + (size_t)warp * HID))[lane] = hp;
}

// ---------------------------------------------------------------------------
// Aggregate (CSR): agg[n] = (sum over incoming edges of hn[src]) * inv_deg[n]
// fp16 gather (256B/row, half the L2 traffic), fp32 accumulation.
// One warp per node; lane covers 4 halves (uint2).
// ---------------------------------------------------------------------------
__global__ void k_agg() {
    int node = (blockIdx.x * blockDim.x + threadIdx.x) >> 5;
    int lane = threadIdx.x & 31;
    if (node >= N_NODES) return;

    int beg = g_off[node];
    int end = g_off[node + 1];
    float4 acc0 = make_float4(0.f, 0.f, 0.f, 0.f);
    float4 acc1 = make_float4(0.f, 0.f, 0.f, 0.f);

    for (int e = beg; e < end; e += 32) {
        int rem = end - e;
        if (rem > 32) rem = 32;
        int sidx = (lane < rem) ? g_esrc[e + lane] : 0;
        int j = 0;
        for (; j + 4 <= rem; j += 4) {
            int s0 = __shfl_sync(0xFFFFFFFFu, sidx, j + 0);
            int s1 = __shfl_sync(0xFFFFFFFFu, sidx, j + 1);
            int s2 = __shfl_sync(0xFFFFFFFFu, sidx, j + 2);
            int s3 = __shfl_sync(0xFFFFFFFFu, sidx, j + 3);
            uint2 u0 = ((const uint2*)(g_hnh + (size_t)s0 * HID))[lane];
            uint2 u1 = ((const uint2*)(g_hnh + (size_t)s1 * HID))[lane];
            uint2 u2 = ((const uint2*)(g_hnh + (size_t)s2 * HID))[lane];
            uint2 u3 = ((const uint2*)(g_hnh + (size_t)s3 * HID))[lane];
            float2 f;
            f = __half22float2(*(__half2*)&u0.x); acc0.x += f.x; acc0.y += f.y;
            f = __half22float2(*(__half2*)&u0.y); acc0.z += f.x; acc0.w += f.y;
            f = __half22float2(*(__half2*)&u1.x); acc1.x += f.x; acc1.y += f.y;
            f = __half22float2(*(__half2*)&u1.y); acc1.z += f.x; acc1.w += f.y;
            f = __half22float2(*(__half2*)&u2.x); acc0.x += f.x; acc0.y += f.y;
            f = __half22float2(*(__half2*)&u2.y); acc0.z += f.x; acc0.w += f.y;
            f = __half22float2(*(__half2*)&u3.x); acc1.x += f.x; acc1.y += f.y;
            f = __half22float2(*(__half2*)&u3.y); acc1.z += f.x; acc1.w += f.y;
        }
        for (; j < rem; j++) {
            int s = __shfl_sync(0xFFFFFFFFu, sidx, j);
            uint2 u = ((const uint2*)(g_hnh + (size_t)s * HID))[lane];
            float2 f;
            f = __half22float2(*(__half2*)&u.x); acc0.x += f.x; acc0.y += f.y;
            f = __half22float2(*(__half2*)&u.y); acc0.z += f.x; acc0.w += f.y;
        }
    }

    float inv = g_inv[node];
    float4 acc;
    acc.x = (acc0.x + acc1.x) * inv;
    acc.y = (acc0.y + acc1.y) * inv;
    acc.z = (acc0.z + acc1.z) * inv;
    acc.w = (acc0.w + acc1.w) * inv;
    ((float4*)(g_agg + (size_t)node * HID))[lane] = acc;
}

// ---------------------------------------------------------------------------
// Layer GEMM via mma.sync bf16x3:  h = relu(h + [agg | hn] @ Wcat + bl)
// CTA tile 128x128, K=256 in 16 chunks of 16. 512 threads = 16 warps (4x4),
// warp tile 32x32. 2-stage smem double buffer, 48B pitch.
// ---------------------------------------------------------------------------
#define LPITCH 48
#define STG    6144          // 128 rows * 48B, one stage of one array
#define SM_A_HI 0
#define SM_A_LO 12288
#define SM_B_HI 24576
#define SM_B_LO 36864
#define LAYER_SMEM 49152

__global__ void __launch_bounds__(512) k_layer(int l, const float* __restrict__ bl) {
    extern __shared__ char sm[];
    int tid = threadIdx.x;
    int lane = tid & 31, wid = tid >> 5;
    int wm = wid & 3, wn = wid >> 2;
    int m0 = blockIdx.x * 128;

    const __nv_bfloat16* Bh_ = g_Bhi + (size_t)l * HID * 2 * HID;
    const __nv_bfloat16* Bl_ = g_Blo + (size_t)l * HID * 2 * HID;

    float C[2][4][4];
#pragma unroll
    for (int mt = 0; mt < 2; mt++)
#pragma unroll
        for (int nt = 0; nt < 4; nt++)
#pragma unroll
            for (int j = 0; j < 4; j++) C[mt][nt][j] = 0.0f;

    int s_r = tid >> 2, s_q = tid & 3;
    int arow = m0 + s_r;
    if (arow >= N_NODES) arow = N_NODES - 1;

    float4 av;
    uint2 bhv, blv;
    av  = *(const float4*)(g_agg + (size_t)arow * HID + s_q * 4);
    bhv = *(const uint2*)(Bh_ + (size_t)s_r * 256 + s_q * 4);
    blv = *(const uint2*)(Bl_ + (size_t)s_r * 256 + s_q * 4);

    for (int c = 0; c < 16; c++) {
        int st = c & 1;
        char* Ah = sm + SM_A_HI + st * STG;
        char* Al = sm + SM_A_LO + st * STG;
        char* Bh = sm + SM_B_HI + st * STG;
        char* Bl = sm + SM_B_LO + st * STG;

        {
            __nv_bfloat162 h0 = __floats2bfloat162_rn(av.x, av.y);
            __nv_bfloat162 h1 = __floats2bfloat162_rn(av.z, av.w);
            float lx = av.x - __bfloat162float(h0.x);
            float ly = av.y - __bfloat162float(h0.y);
            float lz = av.z - __bfloat162float(h1.x);
            float lw = av.w - __bfloat162float(h1.y);
            __nv_bfloat162 l0 = __floats2bfloat162_rn(lx, ly);
            __nv_bfloat162 l1 = __floats2bfloat162_rn(lz, lw);
            uint2 ph, pl;
            ph.x = *(uint32_t*)&h0; ph.y = *(uint32_t*)&h1;
            pl.x = *(uint32_t*)&l0; pl.y = *(uint32_t*)&l1;
            *(uint2*)(Ah + s_r * LPITCH + s_q * 8) = ph;
            *(uint2*)(Al + s_r * LPITCH + s_q * 8) = pl;
            *(uint2*)(Bh + s_r * LPITCH + s_q * 8) = bhv;
            *(uint2*)(Bl + s_r * LPITCH + s_q * 8) = blv;
        }
        __syncthreads();

        if (c < 15) {
            int cn = c + 1;
            const float* Asrc = (cn < 8) ? (g_agg + cn * 16) : (g_hn + (cn - 8) * 16);
            av  = *(const float4*)(Asrc + (size_t)arow * HID + s_q * 4);
            bhv = *(const uint2*)(Bh_ + (size_t)s_r * 256 + cn * 16 + s_q * 4);
            blv = *(const uint2*)(Bl_ + (size_t)s_r * 256 + cn * 16 + s_q * 4);
        }

        uint32_t a_hi[2][4], a_lo[2][4], b_hi[4][2], b_lo[4][2];
#pragma unroll
        for (int mt = 0; mt < 2; mt++) {
            int off = (wm * 32 + mt * 16 + (lane >> 2)) * LPITCH + (lane & 3) * 4;
            a_hi[mt][0] = *(uint32_t*)(Ah + off);
            a_hi[mt][1] = *(uint32_t*)(Ah + off + 8 * LPITCH);
            a_hi[mt][2] = *(uint32_t*)(Ah + off + 16);
            a_hi[mt][3] = *(uint32_t*)(Ah + off + 8 * LPITCH + 16);
            a_lo[mt][0] = *(uint32_t*)(Al + off);
            a_lo[mt][1] = *(uint32_t*)(Al + off + 8 * LPITCH);
            a_lo[mt][2] = *(uint32_t*)(Al + off + 16);
            a_lo[mt][3] = *(uint32_t*)(Al + off + 8 * LPITCH + 16);
        }
#pragma unroll
        for (int nt = 0; nt < 4; nt++) {
            int off = (wn * 32 + nt * 8 + (lane >> 2)) * LPITCH + (lane & 3) * 4;
            b_hi[nt][0] = *(uint32_t*)(Bh + off);
            b_hi[nt][1] = *(uint32_t*)(Bh + off + 16);
            b_lo[nt][0] = *(uint32_t*)(Bl + off);
            b_lo[nt][1] = *(uint32_t*)(Bl + off + 16);
        }

#pragma unroll
        for (int mt = 0; mt < 2; mt++)
#pragma unroll
            for (int nt = 0; nt < 4; nt++) {
                mma_bf16(C[mt][nt], a_hi[mt], b_hi[nt]);
                mma_bf16(C[mt][nt], a_hi[mt], b_lo[nt]);
                mma_bf16(C[mt][nt], a_lo[mt], b_hi[nt]);
            }
        __syncthreads();
    }

    // Epilogue: residual + bias + relu into g_h
#pragma unroll
    for (int mt = 0; mt < 2; mt++) {
        int r0 = m0 + wm * 32 + mt * 16 + (lane >> 2);
#pragma unroll
        for (int half = 0; half < 2; half++) {
            int r = r0 + half * 8;
            if (r < N_NODES) {
#pragma unroll
                for (int nt = 0; nt < 4; nt++) {
                    int cb = wn * 32 + nt * 8 + (lane & 3) * 2;
                    float* hp = g_h + (size_t)r * HID + cb;
                    float2 h2 = *(float2*)hp;
                    float2 bb = *(const float2*)(bl + cb);
                    float2 o;
                    o.x = fmaxf(h2.x + C[mt][nt][half * 2 + 0] + bb.x, 0.0f);
                    o.y = fmaxf(h2.y + C[mt][nt][half * 2 + 1] + bb.y, 0.0f);
                    *(float2*)hp = o;
                }
            }
        }
    }
}

// ---------------------------------------------------------------------------
// out = h @ W_out + b_out   (50000 x 128 @ 128 x 4), one warp per node
// ---------------------------------------------------------------------------
__global__ void k_out(const float* __restrict__ Wo,
                      const float* __restrict__ bo,
                      float* __restrict__ out) {
    __shared__ float Ws[HID * D_OUT];
    int tid = threadIdx.x;
    for (int i = tid; i < HID * D_OUT; i += blockDim.x) Ws[i] = Wo[i];
    __syncthreads();

    int warp = (blockIdx.x * blockDim.x + tid) >> 5;
    int lane = tid & 31;
    if (warp >= N_NODES) return;

    const float* hr = g_h + (size_t)warp * HID;
    float a0 = 0.f, a1 = 0.f, a2 = 0.f, a3 = 0.f;
#pragma unroll
    for (int t = 0; t < 4; t++) {
        int k = lane + t * 32;
        float hv = hr[k];
        a0 += hv * Ws[k * D_OUT + 0];
        a1 += hv * Ws[k * D_OUT + 1];
        a2 += hv * Ws[k * D_OUT + 2];
        a3 += hv * Ws[k * D_OUT + 3];
    }
#pragma unroll
    for (int o = 16; o; o >>= 1) {
        a0 += __shfl_xor_sync(0xFFFFFFFFu, a0, o);
        a1 += __shfl_xor_sync(0xFFFFFFFFu, a1, o);
        a2 += __shfl_xor_sync(0xFFFFFFFFu, a2, o);
        a3 += __shfl_xor_sync(0xFFFFFFFFu, a3, o);
    }
    if (lane == 0) {
        float4 r;
        r.x = a0 + bo[0];
        r.y = a1 + bo[1];
        r.z = a2 + bo[2];
        r.w = a3 + bo[3];
        *(float4*)(out + (size_t)warp * D_OUT) = r;
    }
}

// ---------------------------------------------------------------------------
extern "C" void kernel_launch(void* const* d_in, const int* in_sizes, int n_in,
                              void* d_out, int out_size) {
    const float* x     = (const float*)d_in[0];
    const int*   ei    = (const int*)  d_in[1];
    const float* W_in  = (const float*)d_in[2];
    const float* b_in  = (const float*)d_in[3];
    const float* Wl    = (const float*)d_in[4];
    const float* bl    = (const float*)d_in[5];
    const float* Wr    = (const float*)d_in[6];
    const float* ln_g  = (const float*)d_in[7];
    const float* ln_b  = (const float*)d_in[8];
    const float* W_out = (const float*)d_in[9];
    const float* b_out = (const float*)d_in[10];
    float* out = (float*)d_out;

    const int* src = ei;             // edge_index[0]
    const int* dst = ei + N_EDGES;   // edge_index[1]

    cudaFuncSetAttribute(k_layer, cudaFuncAttributeMaxDynamicSharedMemorySize, LAYER_SMEM);

    // CSR build
    k_zero_cnt<<<(N_NODES + 255) / 256, 256>>>();
    k_count<<<(N_EDGES + 255) / 256, 256>>>(dst);
    k_scan1<<<SCAN_BLOCKS, 256>>>();
    k_scan2<<<1, 256>>>();
    k_scan3<<<SCAN_BLOCKS, 256>>>();
    k_fill<<<(N_EDGES + 255) / 256, 256>>>(src, dst);

    // Weight transpose + bf16 hi/lo split (once per call)
    {
        dim3 g(256 / 32, 128 / 32, N_LAYERS);
        dim3 b(32, 8);
        k_wsplit<<<g, b>>>(Wl, Wr);
    }

    k_in_gemm<<<N_NODES / 16, 256>>>(x, W_in, b_in);

    for (int l = 0; l < N_LAYERS; l++) {
        k_ln<<<(N_NODES * 32 + 255) / 256, 256>>>(ln_g + l * HID, ln_b + l * HID);
        k_agg<<<(N_NODES * 32 + 255) / 256, 256>>>();
        k_layer<<<(N_NODES + 127) / 128, 512, LAYER_SMEM>>>(l, bl + l * HID);
    }

    k_out<<<(N_NODES * 32 + 255) / 256, 256>>>(W_out, b_out, out);
}

// round 9
// speedup vs baseline: 1.1025x; 1.0705x over previous
#include <cuda_runtime.h>
#include <cuda_bf16.h>
#include <cuda_fp16.h>
#include <cstdint>

#define N_NODES 50000
#define N_EDGES 800000
#define D_IN    16
#define HID     128
#define D_OUT   4
#define N_LAYERS 3
#define LN_EPS  1e-5f

#define SCAN_BLOCKS 196   // ceil(50000/256)

// Scratch (device globals: allocation-free, graph-capturable)
__device__ float  g_h   [N_NODES * HID];
__device__ __half g_hnh [N_NODES * HID];   // fp16 LN output (gather + GEMM operand)
__device__ float  g_agg [N_NODES * HID];
__device__ __nv_bfloat16 g_Bhi[N_LAYERS * HID * 2 * HID];  // [l][n=128][k=256]
__device__ __nv_bfloat16 g_Blo[N_LAYERS * HID * 2 * HID];
__device__ float g_inv [N_NODES];
__device__ int   g_cnt [N_NODES];
__device__ int   g_off [N_NODES + 1];
__device__ int   g_cur [N_NODES];
__device__ int   g_bsum[SCAN_BLOCKS];
__device__ int   g_bpre[SCAN_BLOCKS];
__device__ int   g_esrc[N_EDGES];

// ---------------------------------------------------------------------------
// bf16 mma.sync (base PTX, works on compute_103): D += A(16x16) * B(16x8)
// ---------------------------------------------------------------------------
__device__ __forceinline__ void mma_bf16(float* c, const uint32_t* a, const uint32_t* b) {
    asm volatile(
        "mma.sync.aligned.m16n8k16.row.col.f32.bf16.bf16.f32 "
        "{%0,%1,%2,%3}, {%4,%5,%6,%7}, {%8,%9}, {%0,%1,%2,%3};"
        : "+f"(c[0]), "+f"(c[1]), "+f"(c[2]), "+f"(c[3])
        : "r"(a[0]), "r"(a[1]), "r"(a[2]), "r"(a[3]), "r"(b[0]), "r"(b[1]));
}

// ---------------------------------------------------------------------------
// CSR build: histogram -> scan -> fill
// ---------------------------------------------------------------------------
__global__ void k_zero_cnt() {
    int i = blockIdx.x * blockDim.x + threadIdx.x;
    if (i < N_NODES) g_cnt[i] = 0;
}

__global__ void k_count(const int* __restrict__ dst) {
    int e = blockIdx.x * blockDim.x + threadIdx.x;
    if (e < N_EDGES) atomicAdd(&g_cnt[dst[e]], 1);
}

__global__ void k_scan1() {
    __shared__ int s[2][256];
    int b = blockIdx.x, t = threadIdx.x;
    int i = b * 256 + t;
    int v = (i < N_NODES) ? g_cnt[i] : 0;
    s[0][t] = v;
    __syncthreads();
    int p = 0;
#pragma unroll
    for (int off = 1; off < 256; off <<= 1) {
        int nv = s[p][t] + ((t >= off) ? s[p][t - off] : 0);
        s[p ^ 1][t] = nv;
        __syncthreads();
        p ^= 1;
    }
    if (i < N_NODES) g_off[i] = s[p][t] - v;
    if (t == 255) g_bsum[b] = s[p][255];
}

__global__ void k_scan2() {
    __shared__ int s[2][256];
    int t = threadIdx.x;
    int v = (t < SCAN_BLOCKS) ? g_bsum[t] : 0;
    s[0][t] = v;
    __syncthreads();
    int p = 0;
#pragma unroll
    for (int off = 1; off < 256; off <<= 1) {
        int nv = s[p][t] + ((t >= off) ? s[p][t - off] : 0);
        s[p ^ 1][t] = nv;
        __syncthreads();
        p ^= 1;
    }
    if (t < SCAN_BLOCKS) g_bpre[t] = s[p][t] - v;
}

__global__ void k_scan3() {
    int i = blockIdx.x * blockDim.x + threadIdx.x;
    if (i < N_NODES) {
        int o = g_off[i] + g_bpre[i >> 8];
        g_off[i] = o;
        g_cur[i] = o;
        g_inv[i] = 1.0f / fmaxf((float)g_cnt[i], 1.0f);
    }
    if (i == 0) g_off[N_NODES] = N_EDGES;
}

__global__ void k_fill(const int* __restrict__ src, const int* __restrict__ dst) {
    int e = blockIdx.x * blockDim.x + threadIdx.x;
    if (e < N_EDGES) {
        int pos = atomicAdd(&g_cur[dst[e]], 1);
        g_esrc[pos] = src[e];
    }
}

// ---------------------------------------------------------------------------
// Weight transpose + bf16 hi/lo split:
// g_Bhi/lo[l][n][k] from Wcat[k][n] = (k<128 ? Wl[l][k][n] : Wr[l][k-128][n])
// ---------------------------------------------------------------------------
__global__ void k_wsplit(const float* __restrict__ Wl, const float* __restrict__ Wr) {
    __shared__ float s[32][33];
    int K0 = blockIdx.x * 32;
    int N0 = blockIdx.y * 32;
    int l = blockIdx.z;
    int tx = threadIdx.x, ty = threadIdx.y;
    const float* WlL = Wl + l * HID * HID;
    const float* WrL = Wr + l * HID * HID;
#pragma unroll
    for (int i = 0; i < 4; i++) {
        int k = K0 + ty + i * 8;
        int n = N0 + tx;
        s[ty + i * 8][tx] = (k < HID) ? WlL[k * HID + n] : WrL[(k - HID) * HID + n];
    }
    __syncthreads();
    __nv_bfloat16* Oh = g_Bhi + (size_t)l * HID * 2 * HID;
    __nv_bfloat16* Ol = g_Blo + (size_t)l * HID * 2 * HID;
#pragma unroll
    for (int i = 0; i < 4; i++) {
        int n = N0 + ty + i * 8;
        int k = K0 + tx;
        float v = s[tx][ty + i * 8];
        __nv_bfloat16 hi = __float2bfloat16_rn(v);
        Oh[(size_t)n * 256 + k] = hi;
        Ol[(size_t)n * 256 + k] = __float2bfloat16_rn(v - __bfloat162float(hi));
    }
}

// ---------------------------------------------------------------------------
// h = x @ W_in + b_in    (50000 x 16 @ 16 x 128)
// ---------------------------------------------------------------------------
__global__ void k_in_gemm(const float* __restrict__ x,
                          const float* __restrict__ W,
                          const float* __restrict__ b) {
    __shared__ float xs[16][D_IN];
    __shared__ float Ws[D_IN][HID];
    int tid = threadIdx.x;
    int m0 = blockIdx.x * 16;

#pragma unroll
    for (int i = 0; i < 2; i++) {
        int idx = tid + i * 256;
        ((float4*)&Ws[0][0])[idx] = ((const float4*)W)[idx];
    }
    {
        int r = tid >> 4, k = tid & 15;
        xs[r][k] = x[(size_t)(m0 + r) * D_IN + k];
    }
    __syncthreads();

    int col = tid & 127;
    int rh  = tid >> 7;
    float wc[D_IN];
#pragma unroll
    for (int k = 0; k < D_IN; k++) wc[k] = Ws[k][col];
    float bb = b[col];

#pragma unroll
    for (int r = 0; r < 8; r++) {
        int row = rh * 8 + r;
        float acc = bb;
#pragma unroll
        for (int k = 0; k < D_IN; k++) acc += xs[row][k] * wc[k];
        g_h[(size_t)(m0 + row) * HID + col] = acc;
    }
}

// ---------------------------------------------------------------------------
// LayerNorm: hn = LN(h) * g + b, written fp16 only (gather + GEMM operand).
// One warp per row; lane handles a float4.
// ---------------------------------------------------------------------------
__global__ void k_ln(const float* __restrict__ g, const float* __restrict__ b) {
    int warp = (blockIdx.x * blockDim.x + threadIdx.x) >> 5;
    int lane = threadIdx.x & 31;
    if (warp >= N_NODES) return;

    float4 v = ((const float4*)(g_h + (size_t)warp * HID))[lane];
    float s = v.x + v.y + v.z + v.w;
#pragma unroll
    for (int o = 16; o; o >>= 1) s += __shfl_xor_sync(0xFFFFFFFFu, s, o);
    float mu = s * (1.0f / HID);

    float dx = v.x - mu, dy = v.y - mu, dz = v.z - mu, dw = v.w - mu;
    float q = dx * dx + dy * dy + dz * dz + dw * dw;
#pragma unroll
    for (int o = 16; o; o >>= 1) q += __shfl_xor_sync(0xFFFFFFFFu, q, o);
    float rs = rsqrtf(q * (1.0f / HID) + LN_EPS);

    int c = lane * 4;
    float4 gg = *(const float4*)(g + c);
    float4 bb = *(const float4*)(b + c);
    float ox = dx * rs * gg.x + bb.x;
    float oy = dy * rs * gg.y + bb.y;
    float oz = dz * rs * gg.z + bb.z;
    float ow = dw * rs * gg.w + bb.w;

    __half2 hh0 = __floats2half2_rn(ox, oy);
    __half2 hh1 = __floats2half2_rn(oz, ow);
    uint2 hp;
    hp.x = *(uint32_t*)&hh0;
    hp.y = *(uint32_t*)&hh1;
    ((uint2*)(g_hnh + (size_t)warp * HID))[lane] = hp;
}

// ---------------------------------------------------------------------------
// Aggregate (CSR): agg[n] = (sum over incoming edges of hn[src]) * inv_deg[n]
// fp16 gather, fp32 accumulation. Simple dynamic loop (R5 shape, low regs).
// ---------------------------------------------------------------------------
__global__ void k_agg() {
    int node = (blockIdx.x * blockDim.x + threadIdx.x) >> 5;
    int lane = threadIdx.x & 31;
    if (node >= N_NODES) return;

    int beg = g_off[node];
    int end = g_off[node + 1];
    float4 acc = make_float4(0.f, 0.f, 0.f, 0.f);

    for (int e = beg; e < end; e += 32) {
        int rem = end - e;
        int sidx = (lane < rem) ? g_esrc[e + lane] : 0;
        int cnt = rem < 32 ? rem : 32;
#pragma unroll 4
        for (int j = 0; j < cnt; j++) {
            int s = __shfl_sync(0xFFFFFFFFu, sidx, j);
            uint2 u = ((const uint2*)(g_hnh + (size_t)s * HID))[lane];
            float2 f0 = __half22float2(*(__half2*)&u.x);
            float2 f1 = __half22float2(*(__half2*)&u.y);
            acc.x += f0.x; acc.y += f0.y; acc.z += f1.x; acc.w += f1.y;
        }
    }

    float inv = g_inv[node];
    acc.x *= inv; acc.y *= inv; acc.z *= inv; acc.w *= inv;
    ((float4*)(g_agg + (size_t)node * HID))[lane] = acc;
}

// ---------------------------------------------------------------------------
// Layer GEMM via mma.sync bf16x3:  h = relu(h + [agg | hn] @ Wcat + bl)
// CTA tile 128x128, K=256 in 16 chunks of 16. 512 threads = 16 warps (4x4),
// warp tile 32x32. 2-stage smem double buffer, 48B pitch.
// A chunks 0-7 from fp32 g_agg; chunks 8-15 from fp16 g_hnh (exact hi/lo split).
// ---------------------------------------------------------------------------
#define LPITCH 48
#define STG    6144          // 128 rows * 48B, one stage of one array
#define SM_A_HI 0
#define SM_A_LO 12288
#define SM_B_HI 24576
#define SM_B_LO 36864
#define LAYER_SMEM 49152

__global__ void __launch_bounds__(512) k_layer(int l, const float* __restrict__ bl) {
    extern __shared__ char sm[];
    int tid = threadIdx.x;
    int lane = tid & 31, wid = tid >> 5;
    int wm = wid & 3, wn = wid >> 2;
    int m0 = blockIdx.x * 128;

    const __nv_bfloat16* Bh_ = g_Bhi + (size_t)l * HID * 2 * HID;
    const __nv_bfloat16* Bl_ = g_Blo + (size_t)l * HID * 2 * HID;

    float C[2][4][4];
#pragma unroll
    for (int mt = 0; mt < 2; mt++)
#pragma unroll
        for (int nt = 0; nt < 4; nt++)
#pragma unroll
            for (int j = 0; j < 4; j++) C[mt][nt][j] = 0.0f;

    int s_r = tid >> 2, s_q = tid & 3;
    int arow = m0 + s_r;
    if (arow >= N_NODES) arow = N_NODES - 1;

    float4 av;
    uint2 bhv, blv;
    av  = *(const float4*)(g_agg + (size_t)arow * HID + s_q * 4);
    bhv = *(const uint2*)(Bh_ + (size_t)s_r * 256 + s_q * 4);
    blv = *(const uint2*)(Bl_ + (size_t)s_r * 256 + s_q * 4);

    for (int c = 0; c < 16; c++) {
        int st = c & 1;
        char* Ah = sm + SM_A_HI + st * STG;
        char* Al = sm + SM_A_LO + st * STG;
        char* Bh = sm + SM_B_HI + st * STG;
        char* Bl = sm + SM_B_LO + st * STG;

        {
            __nv_bfloat162 h0 = __floats2bfloat162_rn(av.x, av.y);
            __nv_bfloat162 h1 = __floats2bfloat162_rn(av.z, av.w);
            float lx = av.x - __bfloat162float(h0.x);
            float ly = av.y - __bfloat162float(h0.y);
            float lz = av.z - __bfloat162float(h1.x);
            float lw = av.w - __bfloat162float(h1.y);
            __nv_bfloat162 l0 = __floats2bfloat162_rn(lx, ly);
            __nv_bfloat162 l1 = __floats2bfloat162_rn(lz, lw);
            uint2 ph, pl;
            ph.x = *(uint32_t*)&h0; ph.y = *(uint32_t*)&h1;
            pl.x = *(uint32_t*)&l0; pl.y = *(uint32_t*)&l1;
            *(uint2*)(Ah + s_r * LPITCH + s_q * 8) = ph;
            *(uint2*)(Al + s_r * LPITCH + s_q * 8) = pl;
            *(uint2*)(Bh + s_r * LPITCH + s_q * 8) = bhv;
            *(uint2*)(Bl + s_r * LPITCH + s_q * 8) = blv;
        }
        __syncthreads();

        if (c < 15) {
            int cn = c + 1;
            if (cn < 8) {
                av = *(const float4*)(g_agg + (size_t)arow * HID + cn * 16 + s_q * 4);
            } else {
                uint2 u = *(const uint2*)(g_hnh + (size_t)arow * HID + (cn - 8) * 16 + s_q * 4);
                float2 f0 = __half22float2(*(__half2*)&u.x);
                float2 f1 = __half22float2(*(__half2*)&u.y);
                av = make_float4(f0.x, f0.y, f1.x, f1.y);
            }
            bhv = *(const uint2*)(Bh_ + (size_t)s_r * 256 + cn * 16 + s_q * 4);
            blv = *(const uint2*)(Bl_ + (size_t)s_r * 256 + cn * 16 + s_q * 4);
        }

        uint32_t a_hi[2][4], a_lo[2][4], b_hi[4][2], b_lo[4][2];
#pragma unroll
        for (int mt = 0; mt < 2; mt++) {
            int off = (wm * 32 + mt * 16 + (lane >> 2)) * LPITCH + (lane & 3) * 4;
            a_hi[mt][0] = *(uint32_t*)(Ah + off);
            a_hi[mt][1] = *(uint32_t*)(Ah + off + 8 * LPITCH);
            a_hi[mt][2] = *(uint32_t*)(Ah + off + 16);
            a_hi[mt][3] = *(uint32_t*)(Ah + off + 8 * LPITCH + 16);
            a_lo[mt][0] = *(uint32_t*)(Al + off);
            a_lo[mt][1] = *(uint32_t*)(Al + off + 8 * LPITCH);
            a_lo[mt][2] = *(uint32_t*)(Al + off + 16);
            a_lo[mt][3] = *(uint32_t*)(Al + off + 8 * LPITCH + 16);
        }
#pragma unroll
        for (int nt = 0; nt < 4; nt++) {
            int off = (wn * 32 + nt * 8 + (lane >> 2)) * LPITCH + (lane & 3) * 4;
            b_hi[nt][0] = *(uint32_t*)(Bh + off);
            b_hi[nt][1] = *(uint32_t*)(Bh + off + 16);
            b_lo[nt][0] = *(uint32_t*)(Bl + off);
            b_lo[nt][1] = *(uint32_t*)(Bl + off + 16);
        }

#pragma unroll
        for (int mt = 0; mt < 2; mt++)
#pragma unroll
            for (int nt = 0; nt < 4; nt++) {
                mma_bf16(C[mt][nt], a_hi[mt], b_hi[nt]);
                mma_bf16(C[mt][nt], a_hi[mt], b_lo[nt]);
                mma_bf16(C[mt][nt], a_lo[mt], b_hi[nt]);
            }
        __syncthreads();
    }

    // Epilogue: residual + bias + relu into g_h
#pragma unroll
    for (int mt = 0; mt < 2; mt++) {
        int r0 = m0 + wm * 32 + mt * 16 + (lane >> 2);
#pragma unroll
        for (int half = 0; half < 2; half++) {
            int r = r0 + half * 8;
            if (r < N_NODES) {
#pragma unroll
                for (int nt = 0; nt < 4; nt++) {
                    int cb = wn * 32 + nt * 8 + (lane & 3) * 2;
                    float* hp = g_h + (size_t)r * HID + cb;
                    float2 h2 = *(float2*)hp;
                    float2 bb = *(const float2*)(bl + cb);
                    float2 o;
                    o.x = fmaxf(h2.x + C[mt][nt][half * 2 + 0] + bb.x, 0.0f);
                    o.y = fmaxf(h2.y + C[mt][nt][half * 2 + 1] + bb.y, 0.0f);
                    *(float2*)hp = o;
                }
            }
        }
    }
}

// ---------------------------------------------------------------------------
// out = h @ W_out + b_out   (50000 x 128 @ 128 x 4), one warp per node
// ---------------------------------------------------------------------------
__global__ void k_out(const float* __restrict__ Wo,
                      const float* __restrict__ bo,
                      float* __restrict__ out) {
    __shared__ float Ws[HID * D_OUT];
    int tid = threadIdx.x;
    for (int i = tid; i < HID * D_OUT; i += blockDim.x) Ws[i] = Wo[i];
    __syncthreads();

    int warp = (blockIdx.x * blockDim.x + tid) >> 5;
    int lane = tid & 31;
    if (warp >= N_NODES) return;

    const float* hr = g_h + (size_t)warp * HID;
    float a0 = 0.f, a1 = 0.f, a2 = 0.f, a3 = 0.f;
#pragma unroll
    for (int t = 0; t < 4; t++) {
        int k = lane + t * 32;
        float hv = hr[k];
        a0 += hv * Ws[k * D_OUT + 0];
        a1 += hv * Ws[k * D_OUT + 1];
        a2 += hv * Ws[k * D_OUT + 2];
        a3 += hv * Ws[k * D_OUT + 3];
    }
#pragma unroll
    for (int o = 16; o; o >>= 1) {
        a0 += __shfl_xor_sync(0xFFFFFFFFu, a0, o);
        a1 += __shfl_xor_sync(0xFFFFFFFFu, a1, o);
        a2 += __shfl_xor_sync(0xFFFFFFFFu, a2, o);
        a3 += __shfl_xor_sync(0xFFFFFFFFu, a3, o);
    }
    if (lane == 0) {
        float4 r;
        r.x = a0 + bo[0];
        r.y = a1 + bo[1];
        r.z = a2 + bo[2];
        r.w = a3 + bo[3];
        *(float4*)(out + (size_t)warp * D_OUT) = r;
    }
}

// ---------------------------------------------------------------------------
extern "C" void kernel_launch(void* const* d_in, const int* in_sizes, int n_in,
                              void* d_out, int out_size) {
    const float* x     = (const float*)d_in[0];
    const int*   ei    = (const int*)  d_in[1];
    const float* W_in  = (const float*)d_in[2];
    const float* b_in  = (const float*)d_in[3];
    const float* Wl    = (const float*)d_in[4];
    const float* bl    = (const float*)d_in[5];
    const float* Wr    = (const float*)d_in[6];
    const float* ln_g  = (const float*)d_in[7];
    const float* ln_b  = (const float*)d_in[8];
    const float* W_out = (const float*)d_in[9];
    const float* b_out = (const float*)d_in[10];
    float* out = (float*)d_out;

    const int* src = ei;             // edge_index[0]
    const int* dst = ei + N_EDGES;   // edge_index[1]

    cudaFuncSetAttribute(k_layer, cudaFuncAttributeMaxDynamicSharedMemorySize, LAYER_SMEM);

    // CSR build
    k_zero_cnt<<<(N_NODES + 255) / 256, 256>>>();
    k_count<<<(N_EDGES + 255) / 256, 256>>>(dst);
    k_scan1<<<SCAN_BLOCKS, 256>>>();
    k_scan2<<<1, 256>>>();
    k_scan3<<<SCAN_BLOCKS, 256>>>();
    k_fill<<<(N_EDGES + 255) / 256, 256>>>(src, dst);

    // Weight transpose + bf16 hi/lo split (once per call)
    {
        dim3 g(256 / 32, 128 / 32, N_LAYERS);
        dim3 b(32, 8);
        k_wsplit<<<g, b>>>(Wl, Wr);
    }

    k_in_gemm<<<N_NODES / 16, 256>>>(x, W_in, b_in);

    for (int l = 0; l < N_LAYERS; l++) {
        k_ln<<<(N_NODES * 32 + 255) / 256, 256>>>(ln_g + l * HID, ln_b + l * HID);
        k_agg<<<(N_NODES * 32 + 255) / 256, 256>>>();
        k_layer<<<(N_NODES + 127) / 128, 512, LAYER_SMEM>>>(l, bl + l * HID);
    }

    k_out<<<(N_NODES * 32 + 255) / 256, 256>>>(W_out, b_out, out);
}

// round 10
// speedup vs baseline: 1.1033x; 1.0007x over previous
#include <cuda_runtime.h>
#include <cuda_bf16.h>
#include <cuda_fp16.h>
#include <cstdint>

#define N_NODES 50000
#define N_EDGES 800000
#define D_IN    16
#define HID     128
#define D_OUT   4
#define N_LAYERS 3
#define LN_EPS  1e-5f

#define SCAN_BLOCKS 196   // ceil(50000/256)

// Scratch (device globals: allocation-free, graph-capturable).
// g_cnt relies on static zero-init for the first call; every call re-zeroes it
// at the end of k_fill, so all calls see zeros (deterministic across replays).
__device__ float  g_h   [N_NODES * HID];
__device__ __half g_hnh [N_NODES * HID];   // fp16 LN output (gather + GEMM operand)
__device__ float  g_agg [N_NODES * HID];
__device__ __nv_bfloat16 g_Bhi[N_LAYERS * HID * 2 * HID];  // [l][n=128][k=256]
__device__ __nv_bfloat16 g_Blo[N_LAYERS * HID * 2 * HID];
__device__ float g_inv [N_NODES];
__device__ int   g_cnt [N_NODES];
__device__ int   g_off [N_NODES + 1];
__device__ int   g_cur [N_NODES];
__device__ int   g_bsum[SCAN_BLOCKS];
__device__ int   g_esrc[N_EDGES];

// ---------------------------------------------------------------------------
// bf16 mma.sync (base PTX, works on compute_103): D += A(16x16) * B(16x8)
// ---------------------------------------------------------------------------
__device__ __forceinline__ void mma_bf16(float* c, const uint32_t* a, const uint32_t* b) {
    asm volatile(
        "mma.sync.aligned.m16n8k16.row.col.f32.bf16.bf16.f32 "
        "{%0,%1,%2,%3}, {%4,%5,%6,%7}, {%8,%9}, {%0,%1,%2,%3};"
        : "+f"(c[0]), "+f"(c[1]), "+f"(c[2]), "+f"(c[3])
        : "r"(a[0]), "r"(a[1]), "r"(a[2]), "r"(a[3]), "r"(b[0]), "r"(b[1]));
}

// ---------------------------------------------------------------------------
// CSR build (4 launches): count -> scan1 -> scan23 -> fill(+rezero)
// ---------------------------------------------------------------------------
__global__ void k_count(const int* __restrict__ dst) {
    int e = blockIdx.x * blockDim.x + threadIdx.x;
    if (e < N_EDGES) atomicAdd(&g_cnt[dst[e]], 1);
}

__global__ void k_scan1() {
    __shared__ int s[2][256];
    int b = blockIdx.x, t = threadIdx.x;
    int i = b * 256 + t;
    int v = (i < N_NODES) ? g_cnt[i] : 0;
    s[0][t] = v;
    __syncthreads();
    int p = 0;
#pragma unroll
    for (int off = 1; off < 256; off <<= 1) {
        int nv = s[p][t] + ((t >= off) ? s[p][t - off] : 0);
        s[p ^ 1][t] = nv;
        __syncthreads();
        p ^= 1;
    }
    if (i < N_NODES) g_off[i] = s[p][t] - v;
    if (t == 255) g_bsum[b] = s[p][255];
}

// scan2+scan3 fused: each block reduces bsum[0..b) itself.
__global__ void k_scan23() {
    __shared__ int red[256];
    int b = blockIdx.x, t = threadIdx.x;
    int v = (t < b) ? g_bsum[t] : 0;    // t < b <= 195 < SCAN_BLOCKS
    red[t] = v;
    __syncthreads();
#pragma unroll
    for (int off = 128; off; off >>= 1) {
        if (t < off) red[t] += red[t + off];
        __syncthreads();
    }
    int pre = red[0];
    int i = b * 256 + t;
    if (i < N_NODES) {
        int o = g_off[i] + pre;
        g_off[i] = o;
        g_cur[i] = o;
        g_inv[i] = 1.0f / fmaxf((float)g_cnt[i], 1.0f);
    }
    if (i == 0) g_off[N_NODES] = N_EDGES;
}

__global__ void k_fill(const int* __restrict__ src, const int* __restrict__ dst) {
    int e = blockIdx.x * blockDim.x + threadIdx.x;
    if (e < N_EDGES) {
        int pos = atomicAdd(&g_cur[dst[e]], 1);
        g_esrc[pos] = src[e];
    }
    // Re-zero counts for the next call (cnt is not read by this kernel).
    int nt = gridDim.x * blockDim.x;
    for (int i = e; i < N_NODES; i += nt) g_cnt[i] = 0;
}

// ---------------------------------------------------------------------------
// Weight transpose + bf16 hi/lo split:
// g_Bhi/lo[l][n][k] from Wcat[k][n] = (k<128 ? Wl[l][k][n] : Wr[l][k-128][n])
// ---------------------------------------------------------------------------
__global__ void k_wsplit(const float* __restrict__ Wl, const float* __restrict__ Wr) {
    __shared__ float s[32][33];
    int K0 = blockIdx.x * 32;
    int N0 = blockIdx.y * 32;
    int l = blockIdx.z;
    int tx = threadIdx.x, ty = threadIdx.y;
    const float* WlL = Wl + l * HID * HID;
    const float* WrL = Wr + l * HID * HID;
#pragma unroll
    for (int i = 0; i < 4; i++) {
        int k = K0 + ty + i * 8;
        int n = N0 + tx;
        s[ty + i * 8][tx] = (k < HID) ? WlL[k * HID + n] : WrL[(k - HID) * HID + n];
    }
    __syncthreads();
    __nv_bfloat16* Oh = g_Bhi + (size_t)l * HID * 2 * HID;
    __nv_bfloat16* Ol = g_Blo + (size_t)l * HID * 2 * HID;
#pragma unroll
    for (int i = 0; i < 4; i++) {
        int n = N0 + ty + i * 8;
        int k = K0 + tx;
        float v = s[tx][ty + i * 8];
        __nv_bfloat16 hi = __float2bfloat16_rn(v);
        Oh[(size_t)n * 256 + k] = hi;
        Ol[(size_t)n * 256 + k] = __float2bfloat16_rn(v - __bfloat162float(hi));
    }
}

// ---------------------------------------------------------------------------
// h = x @ W_in + b_in    (50000 x 16 @ 16 x 128)
// ---------------------------------------------------------------------------
__global__ void k_in_gemm(const float* __restrict__ x,
                          const float* __restrict__ W,
                          const float* __restrict__ b) {
    __shared__ float xs[16][D_IN];
    __shared__ float Ws[D_IN][HID];
    int tid = threadIdx.x;
    int m0 = blockIdx.x * 16;

#pragma unroll
    for (int i = 0; i < 2; i++) {
        int idx = tid + i * 256;
        ((float4*)&Ws[0][0])[idx] = ((const float4*)W)[idx];
    }
    {
        int r = tid >> 4, k = tid & 15;
        xs[r][k] = x[(size_t)(m0 + r) * D_IN + k];
    }
    __syncthreads();

    int col = tid & 127;
    int rh  = tid >> 7;
    float wc[D_IN];
#pragma unroll
    for (int k = 0; k < D_IN; k++) wc[k] = Ws[k][col];
    float bb = b[col];

#pragma unroll
    for (int r = 0; r < 8; r++) {
        int row = rh * 8 + r;
        float acc = bb;
#pragma unroll
        for (int k = 0; k < D_IN; k++) acc += xs[row][k] * wc[k];
        g_h[(size_t)(m0 + row) * HID + col] = acc;
    }
}

// ---------------------------------------------------------------------------
// LayerNorm: hn = LN(h) * g + b, written fp16 only.
// ---------------------------------------------------------------------------
__global__ void k_ln(const float* __restrict__ g, const float* __restrict__ b) {
    int warp = (blockIdx.x * blockDim.x + threadIdx.x) >> 5;
    int lane = threadIdx.x & 31;
    if (warp >= N_NODES) return;

    float4 v = ((const float4*)(g_h + (size_t)warp * HID))[lane];
    float s = v.x + v.y + v.z + v.w;
#pragma unroll
    for (int o = 16; o; o >>= 1) s += __shfl_xor_sync(0xFFFFFFFFu, s, o);
    float mu = s * (1.0f / HID);

    float dx = v.x - mu, dy = v.y - mu, dz = v.z - mu, dw = v.w - mu;
    float q = dx * dx + dy * dy + dz * dz + dw * dw;
#pragma unroll
    for (int o = 16; o; o >>= 1) q += __shfl_xor_sync(0xFFFFFFFFu, q, o);
    float rs = rsqrtf(q * (1.0f / HID) + LN_EPS);

    int c = lane * 4;
    float4 gg = *(const float4*)(g + c);
    float4 bb = *(const float4*)(b + c);
    float ox = dx * rs * gg.x + bb.x;
    float oy = dy * rs * gg.y + bb.y;
    float oz = dz * rs * gg.z + bb.z;
    float ow = dw * rs * gg.w + bb.w;

    __half2 hh0 = __floats2half2_rn(ox, oy);
    __half2 hh1 = __floats2half2_rn(oz, ow);
    uint2 hp;
    hp.x = *(uint32_t*)&hh0;
    hp.y = *(uint32_t*)&hh1;
    ((uint2*)(g_hnh + (size_t)warp * HID))[lane] = hp;
}

// ---------------------------------------------------------------------------
// Aggregate (CSR): agg[n] = (sum over incoming edges of hn[src]) * inv_deg[n]
// Paired-edge gather: lanes 0-15 cover edge 2j (uint4 = 16B/lane = full 256B
// row), lanes 16-31 cover edge 2j+1. Combine with shfl_xor(16) at the end.
// ---------------------------------------------------------------------------
__global__ void k_agg() {
    int node = (blockIdx.x * blockDim.x + threadIdx.x) >> 5;
    int lane = threadIdx.x & 31;
    if (node >= N_NODES) return;

    int half = lane >> 4;   // 0 or 1: which edge of the pair
    int hl = lane & 15;     // 16B segment within the row

    int beg = g_off[node];
    int end = g_off[node + 1];
    float4 a0 = make_float4(0.f, 0.f, 0.f, 0.f);
    float4 a1 = make_float4(0.f, 0.f, 0.f, 0.f);

    for (int e = beg; e < end; e += 32) {
        int rem = end - e;
        if (rem > 32) rem = 32;
        int sidx = (lane < rem) ? g_esrc[e + lane] : 0;
        int npair = rem >> 1;
#pragma unroll 4
        for (int j = 0; j < npair; j++) {
            int s = __shfl_sync(0xFFFFFFFFu, sidx, 2 * j + half);
            uint4 u = ((const uint4*)(g_hnh + (size_t)s * HID))[hl];
            float2 f;
            f = __half22float2(*(__half2*)&u.x); a0.x += f.x; a0.y += f.y;
            f = __half22float2(*(__half2*)&u.y); a0.z += f.x; a0.w += f.y;
            f = __half22float2(*(__half2*)&u.z); a1.x += f.x; a1.y += f.y;
            f = __half22float2(*(__half2*)&u.w); a1.z += f.x; a1.w += f.y;
        }
        if (rem & 1) {
            int s = __shfl_sync(0xFFFFFFFFu, sidx, rem - 1);
            if (half == 0) {
                uint4 u = ((const uint4*)(g_hnh + (size_t)s * HID))[hl];
                float2 f;
                f = __half22float2(*(__half2*)&u.x); a0.x += f.x; a0.y += f.y;
                f = __half22float2(*(__half2*)&u.y); a0.z += f.x; a0.w += f.y;
                f = __half22float2(*(__half2*)&u.z); a1.x += f.x; a1.y += f.y;
                f = __half22float2(*(__half2*)&u.w); a1.z += f.x; a1.w += f.y;
            }
        }
    }

    // Combine the two edge-halves
    a0.x += __shfl_xor_sync(0xFFFFFFFFu, a0.x, 16);
    a0.y += __shfl_xor_sync(0xFFFFFFFFu, a0.y, 16);
    a0.z += __shfl_xor_sync(0xFFFFFFFFu, a0.z, 16);
    a0.w += __shfl_xor_sync(0xFFFFFFFFu, a0.w, 16);
    a1.x += __shfl_xor_sync(0xFFFFFFFFu, a1.x, 16);
    a1.y += __shfl_xor_sync(0xFFFFFFFFu, a1.y, 16);
    a1.z += __shfl_xor_sync(0xFFFFFFFFu, a1.z, 16);
    a1.w += __shfl_xor_sync(0xFFFFFFFFu, a1.w, 16);

    if (half == 0) {
        float inv = g_inv[node];
        a0.x *= inv; a0.y *= inv; a0.z *= inv; a0.w *= inv;
        a1.x *= inv; a1.y *= inv; a1.z *= inv; a1.w *= inv;
        float* op = g_agg + (size_t)node * HID + hl * 8;
        *(float4*)op = a0;
        *(float4*)(op + 4) = a1;
    }
}

// ---------------------------------------------------------------------------
// Layer GEMM via mma.sync bf16x3:  h = relu(h + [agg | hn] @ Wcat + bl)
// CTA tile 128x128, K=256 in 16 chunks of 16. 512 threads = 16 warps (4x4),
// warp tile 32x32. 2-stage smem double buffer, 48B pitch.
// A chunks 0-7 from fp32 g_agg; chunks 8-15 from fp16 g_hnh (exact hi/lo split).
// ---------------------------------------------------------------------------
#define LPITCH 48
#define STG    6144          // 128 rows * 48B, one stage of one array
#define SM_A_HI 0
#define SM_A_LO 12288
#define SM_B_HI 24576
#define SM_B_LO 36864
#define LAYER_SMEM 49152

__global__ void __launch_bounds__(512) k_layer(int l, const float* __restrict__ bl) {
    extern __shared__ char sm[];
    int tid = threadIdx.x;
    int lane = tid & 31, wid = tid >> 5;
    int wm = wid & 3, wn = wid >> 2;
    int m0 = blockIdx.x * 128;

    const __nv_bfloat16* Bh_ = g_Bhi + (size_t)l * HID * 2 * HID;
    const __nv_bfloat16* Bl_ = g_Blo + (size_t)l * HID * 2 * HID;

    float C[2][4][4];
#pragma unroll
    for (int mt = 0; mt < 2; mt++)
#pragma unroll
        for (int nt = 0; nt < 4; nt++)
#pragma unroll
            for (int j = 0; j < 4; j++) C[mt][nt][j] = 0.0f;

    int s_r = tid >> 2, s_q = tid & 3;
    int arow = m0 + s_r;
    if (arow >= N_NODES) arow = N_NODES - 1;

    float4 av;
    uint2 bhv, blv;
    av  = *(const float4*)(g_agg + (size_t)arow * HID + s_q * 4);
    bhv = *(const uint2*)(Bh_ + (size_t)s_r * 256 + s_q * 4);
    blv = *(const uint2*)(Bl_ + (size_t)s_r * 256 + s_q * 4);

    for (int c = 0; c < 16; c++) {
        int st = c & 1;
        char* Ah = sm + SM_A_HI + st * STG;
        char* Al = sm + SM_A_LO + st * STG;
        char* Bh = sm + SM_B_HI + st * STG;
        char* Bl = sm + SM_B_LO + st * STG;

        {
            __nv_bfloat162 h0 = __floats2bfloat162_rn(av.x, av.y);
            __nv_bfloat162 h1 = __floats2bfloat162_rn(av.z, av.w);
            float lx = av.x - __bfloat162float(h0.x);
            float ly = av.y - __bfloat162float(h0.y);
            float lz = av.z - __bfloat162float(h1.x);
            float lw = av.w - __bfloat162float(h1.y);
            __nv_bfloat162 l0 = __floats2bfloat162_rn(lx, ly);
            __nv_bfloat162 l1 = __floats2bfloat162_rn(lz, lw);
            uint2 ph, pl;
            ph.x = *(uint32_t*)&h0; ph.y = *(uint32_t*)&h1;
            pl.x = *(uint32_t*)&l0; pl.y = *(uint32_t*)&l1;
            *(uint2*)(Ah + s_r * LPITCH + s_q * 8) = ph;
            *(uint2*)(Al + s_r * LPITCH + s_q * 8) = pl;
            *(uint2*)(Bh + s_r * LPITCH + s_q * 8) = bhv;
            *(uint2*)(Bl + s_r * LPITCH + s_q * 8) = blv;
        }
        __syncthreads();

        if (c < 15) {
            int cn = c + 1;
            if (cn < 8) {
                av = *(const float4*)(g_agg + (size_t)arow * HID + cn * 16 + s_q * 4);
            } else {
                uint2 u = *(const uint2*)(g_hnh + (size_t)arow * HID + (cn - 8) * 16 + s_q * 4);
                float2 f0 = __half22float2(*(__half2*)&u.x);
                float2 f1 = __half22float2(*(__half2*)&u.y);
                av = make_float4(f0.x, f0.y, f1.x, f1.y);
            }
            bhv = *(const uint2*)(Bh_ + (size_t)s_r * 256 + cn * 16 + s_q * 4);
            blv = *(const uint2*)(Bl_ + (size_t)s_r * 256 + cn * 16 + s_q * 4);
        }

        uint32_t a_hi[2][4], a_lo[2][4], b_hi[4][2], b_lo[4][2];
#pragma unroll
        for (int mt = 0; mt < 2; mt++) {
            int off = (wm * 32 + mt * 16 + (lane >> 2)) * LPITCH + (lane & 3) * 4;
            a_hi[mt][0] = *(uint32_t*)(Ah + off);
            a_hi[mt][1] = *(uint32_t*)(Ah + off + 8 * LPITCH);
            a_hi[mt][2] = *(uint32_t*)(Ah + off + 16);
            a_hi[mt][3] = *(uint32_t*)(Ah + off + 8 * LPITCH + 16);
            a_lo[mt][0] = *(uint32_t*)(Al + off);
            a_lo[mt][1] = *(uint32_t*)(Al + off + 8 * LPITCH);
            a_lo[mt][2] = *(uint32_t*)(Al + off + 16);
            a_lo[mt][3] = *(uint32_t*)(Al + off + 8 * LPITCH + 16);
        }
#pragma unroll
        for (int nt = 0; nt < 4; nt++) {
            int off = (wn * 32 + nt * 8 + (lane >> 2)) * LPITCH + (lane & 3) * 4;
            b_hi[nt][0] = *(uint32_t*)(Bh + off);
            b_hi[nt][1] = *(uint32_t*)(Bh + off + 16);
            b_lo[nt][0] = *(uint32_t*)(Bl + off);
            b_lo[nt][1] = *(uint32_t*)(Bl + off + 16);
        }

#pragma unroll
        for (int mt = 0; mt < 2; mt++)
#pragma unroll
            for (int nt = 0; nt < 4; nt++) {
                mma_bf16(C[mt][nt], a_hi[mt], b_hi[nt]);
                mma_bf16(C[mt][nt], a_hi[mt], b_lo[nt]);
                mma_bf16(C[mt][nt], a_lo[mt], b_hi[nt]);
            }
        __syncthreads();
    }

    // Epilogue: residual + bias + relu into g_h
#pragma unroll
    for (int mt = 0; mt < 2; mt++) {
        int r0 = m0 + wm * 32 + mt * 16 + (lane >> 2);
#pragma unroll
        for (int half = 0; half < 2; half++) {
            int r = r0 + half * 8;
            if (r < N_NODES) {
#pragma unroll
                for (int nt = 0; nt < 4; nt++) {
                    int cb = wn * 32 + nt * 8 + (lane & 3) * 2;
                    float* hp = g_h + (size_t)r * HID + cb;
                    float2 h2 = *(float2*)hp;
                    float2 bb = *(const float2*)(bl + cb);
                    float2 o;
                    o.x = fmaxf(h2.x + C[mt][nt][half * 2 + 0] + bb.x, 0.0f);
                    o.y = fmaxf(h2.y + C[mt][nt][half * 2 + 1] + bb.y, 0.0f);
                    *(float2*)hp = o;
                }
            }
        }
    }
}

// ---------------------------------------------------------------------------
// out = h @ W_out + b_out   (50000 x 128 @ 128 x 4), one warp per node
// ---------------------------------------------------------------------------
__global__ void k_out(const float* __restrict__ Wo,
                      const float* __restrict__ bo,
                      float* __restrict__ out) {
    __shared__ float Ws[HID * D_OUT];
    int tid = threadIdx.x;
    for (int i = tid; i < HID * D_OUT; i += blockDim.x) Ws[i] = Wo[i];
    __syncthreads();

    int warp = (blockIdx.x * blockDim.x + tid) >> 5;
    int lane = tid & 31;
    if (warp >= N_NODES) return;

    const float* hr = g_h + (size_t)warp * HID;
    float a0 = 0.f, a1 = 0.f, a2 = 0.f, a3 = 0.f;
#pragma unroll
    for (int t = 0; t < 4; t++) {
        int k = lane + t * 32;
        float hv = hr[k];
        a0 += hv * Ws[k * D_OUT + 0];
        a1 += hv * Ws[k * D_OUT + 1];
        a2 += hv * Ws[k * D_OUT + 2];
        a3 += hv * Ws[k * D_OUT + 3];
    }
#pragma unroll
    for (int o = 16; o; o >>= 1) {
        a0 += __shfl_xor_sync(0xFFFFFFFFu, a0, o);
        a1 += __shfl_xor_sync(0xFFFFFFFFu, a1, o);
        a2 += __shfl_xor_sync(0xFFFFFFFFu, a2, o);
        a3 += __shfl_xor_sync(0xFFFFFFFFu, a3, o);
    }
    if (lane == 0) {
        float4 r;
        r.x = a0 + bo[0];
        r.y = a1 + bo[1];
        r.z = a2 + bo[2];
        r.w = a3 + bo[3];
        *(float4*)(out + (size_t)warp * D_OUT) = r;
    }
}

// ---------------------------------------------------------------------------
extern "C" void kernel_launch(void* const* d_in, const int* in_sizes, int n_in,
                              void* d_out, int out_size) {
    const float* x     = (const float*)d_in[0];
    const int*   ei    = (const int*)  d_in[1];
    const float* W_in  = (const float*)d_in[2];
    const float* b_in  = (const float*)d_in[3];
    const float* Wl    = (const float*)d_in[4];
    const float* bl    = (const float*)d_in[5];
    const float* Wr    = (const float*)d_in[6];
    const float* ln_g  = (const float*)d_in[7];
    const float* ln_b  = (const float*)d_in[8];
    const float* W_out = (const float*)d_in[9];
    const float* b_out = (const float*)d_in[10];
    float* out = (float*)d_out;

    const int* src = ei;             // edge_index[0]
    const int* dst = ei + N_EDGES;   // edge_index[1]

    cudaFuncSetAttribute(k_layer, cudaFuncAttributeMaxDynamicSharedMemorySize, LAYER_SMEM);

    // CSR build (g_cnt is zero on entry: static init / re-zeroed by k_fill)
    k_count<<<(N_EDGES + 255) / 256, 256>>>(dst);
    k_scan1<<<SCAN_BLOCKS, 256>>>();
    k_scan23<<<SCAN_BLOCKS, 256>>>();
    k_fill<<<(N_EDGES + 255) / 256, 256>>>(src, dst);

    // Weight transpose + bf16 hi/lo split (once per call)
    {
        dim3 g(256 / 32, 128 / 32, N_LAYERS);
        dim3 b(32, 8);
        k_wsplit<<<g, b>>>(Wl, Wr);
    }

    k_in_gemm<<<N_NODES / 16, 256>>>(x, W_in, b_in);

    for (int l = 0; l < N_LAYERS; l++) {
        k_ln<<<(N_NODES * 32 + 255) / 256, 256>>>(ln_g + l * HID, ln_b + l * HID);
        k_agg<<<(N_NODES * 32 + 255) / 256, 256>>>();
        k_layer<<<(N_NODES + 127) / 128, 512, LAYER_SMEM>>>(l, bl + l * HID);
    }

    k_out<<<(N_NODES * 32 + 255) / 256, 256>>>(W_out, b_out, out);
}

// round 11
// speedup vs baseline: 1.5057x; 1.3647x over previous
#include <cuda_runtime.h>
#include <cuda_fp16.h>
#include <cstdint>

#define N_NODES 50000
#define N_EDGES 800000
#define D_IN    16
#define HID     128
#define D_OUT   4
#define N_LAYERS 3
#define LN_EPS  1e-5f

#define SCAN_BLOCKS 196   // ceil(50000/256)

// Scratch (device globals: allocation-free, graph-capturable).
// g_cnt relies on static zero-init for the first call; every call re-zeroes it
// at the end of k_fill, so all calls see zeros (deterministic across replays).
__device__ float  g_h   [N_NODES * HID];
__device__ __half g_hnh [N_NODES * HID];   // fp16 LN output
__device__ __half g_aggh[N_NODES * HID];   // fp16 aggregate
__device__ __half g_Wh  [N_LAYERS * HID * 2 * HID];  // [l][n=128][k=256] fp16
__device__ float g_inv [N_NODES];
__device__ int   g_cnt [N_NODES];
__device__ int   g_off [N_NODES + 1];
__device__ int   g_cur [N_NODES];
__device__ int   g_bsum[SCAN_BLOCKS];
__device__ int   g_esrc[N_EDGES];

// ---------------------------------------------------------------------------
// fp16 mma.sync (base PTX): D += A(16x16) * B(16x8), fp32 accum
// ---------------------------------------------------------------------------
__device__ __forceinline__ void mma_fp16(float* c, const uint32_t* a, const uint32_t* b) {
    asm volatile(
        "mma.sync.aligned.m16n8k16.row.col.f32.f16.f16.f32 "
        "{%0,%1,%2,%3}, {%4,%5,%6,%7}, {%8,%9}, {%0,%1,%2,%3};"
        : "+f"(c[0]), "+f"(c[1]), "+f"(c[2]), "+f"(c[3])
        : "r"(a[0]), "r"(a[1]), "r"(a[2]), "r"(a[3]), "r"(b[0]), "r"(b[1]));
}

// ---------------------------------------------------------------------------
// CSR build (4 launches): count -> scan1 -> scan23 -> fill(+rezero)
// ---------------------------------------------------------------------------
__global__ void k_count(const int* __restrict__ dst) {
    int e = blockIdx.x * blockDim.x + threadIdx.x;
    if (e < N_EDGES) atomicAdd(&g_cnt[dst[e]], 1);
}

__global__ void k_scan1() {
    __shared__ int s[2][256];
    int b = blockIdx.x, t = threadIdx.x;
    int i = b * 256 + t;
    int v = (i < N_NODES) ? g_cnt[i] : 0;
    s[0][t] = v;
    __syncthreads();
    int p = 0;
#pragma unroll
    for (int off = 1; off < 256; off <<= 1) {
        int nv = s[p][t] + ((t >= off) ? s[p][t - off] : 0);
        s[p ^ 1][t] = nv;
        __syncthreads();
        p ^= 1;
    }
    if (i < N_NODES) g_off[i] = s[p][t] - v;
    if (t == 255) g_bsum[b] = s[p][255];
}

// scan2+scan3 fused: each block reduces bsum[0..b) itself.
__global__ void k_scan23() {
    __shared__ int red[256];
    int b = blockIdx.x, t = threadIdx.x;
    int v = (t < b) ? g_bsum[t] : 0;
    red[t] = v;
    __syncthreads();
#pragma unroll
    for (int off = 128; off; off >>= 1) {
        if (t < off) red[t] += red[t + off];
        __syncthreads();
    }
    int pre = red[0];
    int i = b * 256 + t;
    if (i < N_NODES) {
        int o = g_off[i] + pre;
        g_off[i] = o;
        g_cur[i] = o;
        g_inv[i] = 1.0f / fmaxf((float)g_cnt[i], 1.0f);
    }
    if (i == 0) g_off[N_NODES] = N_EDGES;
}

__global__ void k_fill(const int* __restrict__ src, const int* __restrict__ dst) {
    int e = blockIdx.x * blockDim.x + threadIdx.x;
    if (e < N_EDGES) {
        int pos = atomicAdd(&g_cur[dst[e]], 1);
        g_esrc[pos] = src[e];
    }
    int nt = gridDim.x * blockDim.x;
    for (int i = e; i < N_NODES; i += nt) g_cnt[i] = 0;
}

// ---------------------------------------------------------------------------
// Weight transpose to fp16: g_Wh[l][n][k] from
// Wcat[k][n] = (k<128 ? Wl[l][k][n] : Wr[l][k-128][n])
// ---------------------------------------------------------------------------
__global__ void k_wprep(const float* __restrict__ Wl, const float* __restrict__ Wr) {
    __shared__ float s[32][33];
    int K0 = blockIdx.x * 32;
    int N0 = blockIdx.y * 32;
    int l = blockIdx.z;
    int tx = threadIdx.x, ty = threadIdx.y;
    const float* WlL = Wl + l * HID * HID;
    const float* WrL = Wr + l * HID * HID;
#pragma unroll
    for (int i = 0; i < 4; i++) {
        int k = K0 + ty + i * 8;
        int n = N0 + tx;
        s[ty + i * 8][tx] = (k < HID) ? WlL[k * HID + n] : WrL[(k - HID) * HID + n];
    }
    __syncthreads();
    __half* O = g_Wh + (size_t)l * HID * 2 * HID;
#pragma unroll
    for (int i = 0; i < 4; i++) {
        int n = N0 + ty + i * 8;
        int k = K0 + tx;
        O[(size_t)n * 256 + k] = __float2half_rn(s[tx][ty + i * 8]);
    }
}

// ---------------------------------------------------------------------------
// h = x @ W_in + b_in    (50000 x 16 @ 16 x 128)
// ---------------------------------------------------------------------------
__global__ void k_in_gemm(const float* __restrict__ x,
                          const float* __restrict__ W,
                          const float* __restrict__ b) {
    __shared__ float xs[16][D_IN];
    __shared__ float Ws[D_IN][HID];
    int tid = threadIdx.x;
    int m0 = blockIdx.x * 16;

#pragma unroll
    for (int i = 0; i < 2; i++) {
        int idx = tid + i * 256;
        ((float4*)&Ws[0][0])[idx] = ((const float4*)W)[idx];
    }
    {
        int r = tid >> 4, k = tid & 15;
        xs[r][k] = x[(size_t)(m0 + r) * D_IN + k];
    }
    __syncthreads();

    int col = tid & 127;
    int rh  = tid >> 7;
    float wc[D_IN];
#pragma unroll
    for (int k = 0; k < D_IN; k++) wc[k] = Ws[k][col];
    float bb = b[col];

#pragma unroll
    for (int r = 0; r < 8; r++) {
        int row = rh * 8 + r;
        float acc = bb;
#pragma unroll
        for (int k = 0; k < D_IN; k++) acc += xs[row][k] * wc[k];
        g_h[(size_t)(m0 + row) * HID + col] = acc;
    }
}

// ---------------------------------------------------------------------------
// LayerNorm: hn = LN(h) * g + b, written fp16 only.
// ---------------------------------------------------------------------------
__global__ void k_ln(const float* __restrict__ g, const float* __restrict__ b) {
    int warp = (blockIdx.x * blockDim.x + threadIdx.x) >> 5;
    int lane = threadIdx.x & 31;
    if (warp >= N_NODES) return;

    float4 v = ((const float4*)(g_h + (size_t)warp * HID))[lane];
    float s = v.x + v.y + v.z + v.w;
#pragma unroll
    for (int o = 16; o; o >>= 1) s += __shfl_xor_sync(0xFFFFFFFFu, s, o);
    float mu = s * (1.0f / HID);

    float dx = v.x - mu, dy = v.y - mu, dz = v.z - mu, dw = v.w - mu;
    float q = dx * dx + dy * dy + dz * dz + dw * dw;
#pragma unroll
    for (int o = 16; o; o >>= 1) q += __shfl_xor_sync(0xFFFFFFFFu, q, o);
    float rs = rsqrtf(q * (1.0f / HID) + LN_EPS);

    int c = lane * 4;
    float4 gg = *(const float4*)(g + c);
    float4 bb = *(const float4*)(b + c);
    float ox = dx * rs * gg.x + bb.x;
    float oy = dy * rs * gg.y + bb.y;
    float oz = dz * rs * gg.z + bb.z;
    float ow = dw * rs * gg.w + bb.w;

    __half2 hh0 = __floats2half2_rn(ox, oy);
    __half2 hh1 = __floats2half2_rn(oz, ow);
    uint2 hp;
    hp.x = *(uint32_t*)&hh0;
    hp.y = *(uint32_t*)&hh1;
    ((uint2*)(g_hnh + (size_t)warp * HID))[lane] = hp;
}

// ---------------------------------------------------------------------------
// Aggregate (CSR): aggh[n] = fp16((sum of hn[src]) * inv_deg[n])
// Paired-edge gather: lanes 0-15 cover edge 2j (uint4 = full 256B row),
// lanes 16-31 cover edge 2j+1. Combine with shfl_xor(16) at the end.
// ---------------------------------------------------------------------------
__global__ void k_agg() {
    int node = (blockIdx.x * blockDim.x + threadIdx.x) >> 5;
    int lane = threadIdx.x & 31;
    if (node >= N_NODES) return;

    int half = lane >> 4;
    int hl = lane & 15;

    int beg = g_off[node];
    int end = g_off[node + 1];
    float4 a0 = make_float4(0.f, 0.f, 0.f, 0.f);
    float4 a1 = make_float4(0.f, 0.f, 0.f, 0.f);

    for (int e = beg; e < end; e += 32) {
        int rem = end - e;
        if (rem > 32) rem = 32;
        int sidx = (lane < rem) ? g_esrc[e + lane] : 0;
        int npair = rem >> 1;
#pragma unroll 4
        for (int j = 0; j < npair; j++) {
            int s = __shfl_sync(0xFFFFFFFFu, sidx, 2 * j + half);
            uint4 u = ((const uint4*)(g_hnh + (size_t)s * HID))[hl];
            float2 f;
            f = __half22float2(*(__half2*)&u.x); a0.x += f.x; a0.y += f.y;
            f = __half22float2(*(__half2*)&u.y); a0.z += f.x; a0.w += f.y;
            f = __half22float2(*(__half2*)&u.z); a1.x += f.x; a1.y += f.y;
            f = __half22float2(*(__half2*)&u.w); a1.z += f.x; a1.w += f.y;
        }
        if (rem & 1) {
            int s = __shfl_sync(0xFFFFFFFFu, sidx, rem - 1);
            if (half == 0) {
                uint4 u = ((const uint4*)(g_hnh + (size_t)s * HID))[hl];
                float2 f;
                f = __half22float2(*(__half2*)&u.x); a0.x += f.x; a0.y += f.y;
                f = __half22float2(*(__half2*)&u.y); a0.z += f.x; a0.w += f.y;
                f = __half22float2(*(__half2*)&u.z); a1.x += f.x; a1.y += f.y;
                f = __half22float2(*(__half2*)&u.w); a1.z += f.x; a1.w += f.y;
            }
        }
    }

    a0.x += __shfl_xor_sync(0xFFFFFFFFu, a0.x, 16);
    a0.y += __shfl_xor_sync(0xFFFFFFFFu, a0.y, 16);
    a0.z += __shfl_xor_sync(0xFFFFFFFFu, a0.z, 16);
    a0.w += __shfl_xor_sync(0xFFFFFFFFu, a0.w, 16);
    a1.x += __shfl_xor_sync(0xFFFFFFFFu, a1.x, 16);
    a1.y += __shfl_xor_sync(0xFFFFFFFFu, a1.y, 16);
    a1.z += __shfl_xor_sync(0xFFFFFFFFu, a1.z, 16);
    a1.w += __shfl_xor_sync(0xFFFFFFFFu, a1.w, 16);

    if (half == 0) {
        float inv = g_inv[node];
        __half2 h0 = __floats2half2_rn(a0.x * inv, a0.y * inv);
        __half2 h1 = __floats2half2_rn(a0.z * inv, a0.w * inv);
        __half2 h2 = __floats2half2_rn(a1.x * inv, a1.y * inv);
        __half2 h3 = __floats2half2_rn(a1.z * inv, a1.w * inv);
        uint4 o;
        o.x = *(uint32_t*)&h0; o.y = *(uint32_t*)&h1;
        o.z = *(uint32_t*)&h2; o.w = *(uint32_t*)&h3;
        ((uint4*)(g_aggh + (size_t)node * HID))[hl] = o;
    }
}

// ---------------------------------------------------------------------------
// Layer GEMM, all-fp16 single MMA:  h = relu(h + [aggh | hnh] @ Wh + bl)
// CTA tile 128x128, K=256 in 16 chunks of 16. 512 threads = 16 warps (4x4),
// warp tile 32x32 (2 m-frags x 4 n-frags), 1 MMA each per chunk.
// 2-stage smem double buffer, 48B pitch, pure-copy staging.
// ---------------------------------------------------------------------------
#define LPITCH 48
#define STG    6144          // 128 rows * 48B
#define LAYER_SMEM (4 * STG) // A0,B0,A1,B1 = 24576

__global__ void __launch_bounds__(512) k_layer(int l, const float* __restrict__ bl) {
    extern __shared__ char sm[];
    int tid = threadIdx.x;
    int lane = tid & 31, wid = tid >> 5;
    int wm = wid & 3, wn = wid >> 2;
    int m0 = blockIdx.x * 128;

    const __half* W_ = g_Wh + (size_t)l * HID * 2 * HID;

    float C[2][4][4];
#pragma unroll
    for (int mt = 0; mt < 2; mt++)
#pragma unroll
        for (int nt = 0; nt < 4; nt++)
#pragma unroll
            for (int j = 0; j < 4; j++) C[mt][nt][j] = 0.0f;

    int s_r = tid >> 2, s_q = tid & 3;   // row 0..127, 8B (4 halves) segment 0..3
    int arow = m0 + s_r;
    if (arow >= N_NODES) arow = N_NODES - 1;

    uint2 av, bv;
    av = *(const uint2*)(g_aggh + (size_t)arow * HID + s_q * 4);
    bv = *(const uint2*)(W_ + (size_t)s_r * 256 + s_q * 4);

    for (int c = 0; c < 16; c++) {
        int st = c & 1;
        char* As = sm + st * 2 * STG;
        char* Bs = As + STG;

        *(uint2*)(As + s_r * LPITCH + s_q * 8) = av;
        *(uint2*)(Bs + s_r * LPITCH + s_q * 8) = bv;
        __syncthreads();

        if (c < 15) {
            int cn = c + 1;
            const __half* Asrc = (cn < 8) ? (g_aggh + cn * 16) : (g_hnh + (cn - 8) * 16);
            av = *(const uint2*)(Asrc + (size_t)arow * HID + s_q * 4);
            bv = *(const uint2*)(W_ + (size_t)s_r * 256 + cn * 16 + s_q * 4);
        }

        uint32_t a[2][4], b[4][2];
#pragma unroll
        for (int mt = 0; mt < 2; mt++) {
            int off = (wm * 32 + mt * 16 + (lane >> 2)) * LPITCH + (lane & 3) * 4;
            a[mt][0] = *(uint32_t*)(As + off);
            a[mt][1] = *(uint32_t*)(As + off + 8 * LPITCH);
            a[mt][2] = *(uint32_t*)(As + off + 16);
            a[mt][3] = *(uint32_t*)(As + off + 8 * LPITCH + 16);
        }
#pragma unroll
        for (int nt = 0; nt < 4; nt++) {
            int off = (wn * 32 + nt * 8 + (lane >> 2)) * LPITCH + (lane & 3) * 4;
            b[nt][0] = *(uint32_t*)(Bs + off);
            b[nt][1] = *(uint32_t*)(Bs + off + 16);
        }

#pragma unroll
        for (int mt = 0; mt < 2; mt++)
#pragma unroll
            for (int nt = 0; nt < 4; nt++)
                mma_fp16(C[mt][nt], a[mt], b[nt]);
        __syncthreads();
    }

    // Epilogue: residual + bias + relu into g_h
#pragma unroll
    for (int mt = 0; mt < 2; mt++) {
        int r0 = m0 + wm * 32 + mt * 16 + (lane >> 2);
#pragma unroll
        for (int half = 0; half < 2; half++) {
            int r = r0 + half * 8;
            if (r < N_NODES) {
#pragma unroll
                for (int nt = 0; nt < 4; nt++) {
                    int cb = wn * 32 + nt * 8 + (lane & 3) * 2;
                    float* hp = g_h + (size_t)r * HID + cb;
                    float2 h2 = *(float2*)hp;
                    float2 bb = *(const float2*)(bl + cb);
                    float2 o;
                    o.x = fmaxf(h2.x + C[mt][nt][half * 2 + 0] + bb.x, 0.0f);
                    o.y = fmaxf(h2.y + C[mt][nt][half * 2 + 1] + bb.y, 0.0f);
                    *(float2*)hp = o;
                }
            }
        }
    }
}

// ---------------------------------------------------------------------------
// out = h @ W_out + b_out   (50000 x 128 @ 128 x 4), one warp per node
// ---------------------------------------------------------------------------
__global__ void k_out(const float* __restrict__ Wo,
                      const float* __restrict__ bo,
                      float* __restrict__ out) {
    __shared__ float Ws[HID * D_OUT];
    int tid = threadIdx.x;
    for (int i = tid; i < HID * D_OUT; i += blockDim.x) Ws[i] = Wo[i];
    __syncthreads();

    int warp = (blockIdx.x * blockDim.x + tid) >> 5;
    int lane = tid & 31;
    if (warp >= N_NODES) return;

    const float* hr = g_h + (size_t)warp * HID;
    float a0 = 0.f, a1 = 0.f, a2 = 0.f, a3 = 0.f;
#pragma unroll
    for (int t = 0; t < 4; t++) {
        int k = lane + t * 32;
        float hv = hr[k];
        a0 += hv * Ws[k * D_OUT + 0];
        a1 += hv * Ws[k * D_OUT + 1];
        a2 += hv * Ws[k * D_OUT + 2];
        a3 += hv * Ws[k * D_OUT + 3];
    }
#pragma unroll
    for (int o = 16; o; o >>= 1) {
        a0 += __shfl_xor_sync(0xFFFFFFFFu, a0, o);
        a1 += __shfl_xor_sync(0xFFFFFFFFu, a1, o);
        a2 += __shfl_xor_sync(0xFFFFFFFFu, a2, o);
        a3 += __shfl_xor_sync(0xFFFFFFFFu, a3, o);
    }
    if (lane == 0) {
        float4 r;
        r.x = a0 + bo[0];
        r.y = a1 + bo[1];
        r.z = a2 + bo[2];
        r.w = a3 + bo[3];
        *(float4*)(out + (size_t)warp * D_OUT) = r;
    }
}

// ---------------------------------------------------------------------------
extern "C" void kernel_launch(void* const* d_in, const int* in_sizes, int n_in,
                              void* d_out, int out_size) {
    const float* x     = (const float*)d_in[0];
    const int*   ei    = (const int*)  d_in[1];
    const float* W_in  = (const float*)d_in[2];
    const float* b_in  = (const float*)d_in[3];
    const float* Wl    = (const float*)d_in[4];
    const float* bl    = (const float*)d_in[5];
    const float* Wr    = (const float*)d_in[6];
    const float* ln_g  = (const float*)d_in[7];
    const float* ln_b  = (const float*)d_in[8];
    const float* W_out = (const float*)d_in[9];
    const float* b_out = (const float*)d_in[10];
    float* out = (float*)d_out;

    const int* src = ei;             // edge_index[0]
    const int* dst = ei + N_EDGES;   // edge_index[1]

    cudaFuncSetAttribute(k_layer, cudaFuncAttributeMaxDynamicSharedMemorySize, LAYER_SMEM);

    // CSR build (g_cnt is zero on entry: static init / re-zeroed by k_fill)
    k_count<<<(N_EDGES + 255) / 256, 256>>>(dst);
    k_scan1<<<SCAN_BLOCKS, 256>>>();
    k_scan23<<<SCAN_BLOCKS, 256>>>();
    k_fill<<<(N_EDGES + 255) / 256, 256>>>(src, dst);

    // Weight transpose to fp16 (once per call)
    {
        dim3 g(256 / 32, 128 / 32, N_LAYERS);
        dim3 b(32, 8);
        k_wprep<<<g, b>>>(Wl, Wr);
    }

    k_in_gemm<<<N_NODES / 16, 256>>>(x, W_in, b_in);

    for (int l = 0; l < N_LAYERS; l++) {
        k_ln<<<(N_NODES * 32 + 255) / 256, 256>>>(ln_g + l * HID, ln_b + l * HID);
        k_agg<<<(N_NODES * 32 + 255) / 256, 256>>>();
        k_layer<<<(N_NODES + 127) / 128, 512, LAYER_SMEM>>>(l, bl + l * HID);
    }

    k_out<<<(N_NODES * 32 + 255) / 256, 256>>>(W_out, b_out, out);
}